// round 6
// baseline (speedup 1.0000x reference)
#include <cuda_runtime.h>
#include <cuda_bf16.h>
#include <math.h>

// Problem constants
#define H     96
#define W     96
#define HW    9216           // H*W
#define C     64
#define T     7
#define NB    12             // 6 backward + 6 forward frame pairs
#define CIN1  130            // warped(64) + x_cur(64) + flow(2)
#define COUT4 432            // 3 * 9 * 16
#define NEG   0.1f

// ---------------------------------------------------------------------------
// Packed fp32x2 helpers (sm_100a FFMA2 path — 2 fp32 FMAs per issue slot)
// ---------------------------------------------------------------------------
__device__ __forceinline__ void ffma2(unsigned long long& d,
                                      unsigned long long a,
                                      unsigned long long b) {
    asm("fma.rn.f32x2 %0, %1, %2, %0;" : "+l"(d) : "l"(a), "l"(b));
}
__device__ __forceinline__ unsigned long long pack2(float lo, float hi) {
    unsigned long long r;
    asm("mov.b64 %0, {%1, %2};" : "=l"(r) : "f"(lo), "f"(hi));
    return r;
}
__device__ __forceinline__ float2 unpack2(unsigned long long v) {
    float2 r;
    asm("mov.b64 {%0, %1}, %2;" : "=f"(r.x), "=f"(r.y) : "l"(v));
    return r;
}

// Fast tanh / sigmoid on MUFU EX2/RCP (rel err ~1e-6 — negligible here).
__device__ __forceinline__ float fast_tanh(float x) {
    float xc = fminf(fmaxf(x, -15.f), 15.f);
    float e = __expf(2.f * xc);
    return __fdividef(e - 1.f, e + 1.f);
}
__device__ __forceinline__ float fast_sigmoid(float x) {
    float xc = fminf(fmaxf(x, -30.f), 30.f);
    return __fdividef(1.f, 1.f + __expf(-xc));
}

// ---------------------------------------------------------------------------
// Scratch buffers (device globals -- no allocation allowed in kernel_launch)
// ---------------------------------------------------------------------------
__device__ float g_h0[NB * CIN1 * HW];    // concat input
__device__ float g_h1[NB * C * HW];       // conv1 out / conv3 out
__device__ float g_h2[NB * C * HW];       // conv2 out
__device__ float g_o4[NB * COUT4 * HW];   // conv4 out
__device__ float g_samp[NB * 576 * HW];   // deform samples (255 MB)
__device__ float g_xt[T * HW * C];        // x transposed to NHWC (16.5 MB)

// ---------------------------------------------------------------------------
// Zero only the two frames deform never writes (bwd[6], fwd[0])
// ---------------------------------------------------------------------------
__global__ void zero_k(float4* __restrict__ p, int n4) {
    int i = blockIdx.x * blockDim.x + threadIdx.x;
    if (i < n4) p[i] = make_float4(0.f, 0.f, 0.f, 0.f);
}

// ---------------------------------------------------------------------------
// NCHW -> NHWC transpose of x: g_xt[t][pix][64].
// ---------------------------------------------------------------------------
__global__ void nhwc_k(const float* __restrict__ x, float4* __restrict__ xt4) {
    int p = blockIdx.x * blockDim.x + threadIdx.x;
    if (p >= T * HW) return;
    int t = p / HW, pix = p % HW;
    const float* xn = x + (size_t)t * C * HW + pix;
    float4* dst = xt4 + (size_t)p * (C / 4);
    #pragma unroll
    for (int cb = 0; cb < C / 4; cb++) {
        float4 v;
        v.x = xn[(size_t)(4 * cb + 0) * HW];
        v.y = xn[(size_t)(4 * cb + 1) * HW];
        v.z = xn[(size_t)(4 * cb + 2) * HW];
        v.w = xn[(size_t)(4 * cb + 3) * HW];
        dst[cb] = v;
    }
}

// ---------------------------------------------------------------------------
// Stage 1: flow-warp x_src (NHWC float4 gathers) + concat build.
// ---------------------------------------------------------------------------
__global__ void warp_concat_k(const float* __restrict__ x,
                              const float4* __restrict__ xt4,
                              const float* __restrict__ fb,
                              const float* __restrict__ ff,
                              float* __restrict__ h0) {
    int p = blockIdx.x * blockDim.x + threadIdx.x;
    if (p >= NB * HW) return;
    int n = p / HW, pix = p % HW;
    int yy = pix / W, xx = pix % W;

    int src_t, cur_t;
    const float* flow;
    if (n < 6) { src_t = n + 1; cur_t = n;     flow = fb + (size_t)n * 2 * HW; }
    else       { int m = n - 6; src_t = m; cur_t = m + 1; flow = ff + (size_t)m * 2 * HW; }

    float fx = flow[pix];
    float fy = flow[HW + pix];
    float px = (float)xx + fx;
    float py = (float)yy + fy;

    float y0f = floorf(py), x0f = floorf(px);
    int iy0 = (int)y0f, ix0 = (int)x0f;
    float wy = py - y0f, wx = px - x0f;
    bool vy0 = (iy0 >= 0) && (iy0 < H);
    bool vy1 = (iy0 + 1 >= 0) && (iy0 + 1 < H);
    bool vx0 = (ix0 >= 0) && (ix0 < W);
    bool vx1 = (ix0 + 1 >= 0) && (ix0 + 1 < W);
    int yc0 = min(max(iy0, 0), H - 1),     yc1 = min(max(iy0 + 1, 0), H - 1);
    int xc0 = min(max(ix0, 0), W - 1),     xc1 = min(max(ix0 + 1, 0), W - 1);
    float w00 = (1.f - wy) * (1.f - wx) * ((vy0 && vx0) ? 1.f : 0.f);
    float w01 = (1.f - wy) * wx          * ((vy0 && vx1) ? 1.f : 0.f);
    float w10 = wy * (1.f - wx)          * ((vy1 && vx0) ? 1.f : 0.f);
    float w11 = wy * wx                  * ((vy1 && vx1) ? 1.f : 0.f);
    int i00 = yc0 * W + xc0, i01 = yc0 * W + xc1;
    int i10 = yc1 * W + xc0, i11 = yc1 * W + xc1;

    const float4* s00 = xt4 + ((size_t)src_t * HW + i00) * (C / 4);
    const float4* s01 = xt4 + ((size_t)src_t * HW + i01) * (C / 4);
    const float4* s10 = xt4 + ((size_t)src_t * HW + i10) * (C / 4);
    const float4* s11 = xt4 + ((size_t)src_t * HW + i11) * (C / 4);
    const float* cur = x + (size_t)cur_t * C * HW;
    float* hn = h0 + (size_t)n * CIN1 * HW;

    #pragma unroll 4
    for (int cb = 0; cb < C / 4; cb++) {
        float4 a = s00[cb], b = s01[cb], c = s10[cb], d = s11[cb];
        float4 v;
        v.x = w00 * a.x + w01 * b.x + w10 * c.x + w11 * d.x;
        v.y = w00 * a.y + w01 * b.y + w10 * c.y + w11 * d.y;
        v.z = w00 * a.z + w01 * b.z + w10 * c.z + w11 * d.z;
        v.w = w00 * a.w + w01 * b.w + w10 * c.w + w11 * d.w;
        hn[(size_t)(4 * cb + 0) * HW + pix] = v.x;
        hn[(size_t)(4 * cb + 1) * HW + pix] = v.y;
        hn[(size_t)(4 * cb + 2) * HW + pix] = v.z;
        hn[(size_t)(4 * cb + 3) * HW + pix] = v.w;
        hn[(size_t)(C + 4 * cb + 0) * HW + pix] = cur[(size_t)(4 * cb + 0) * HW + pix];
        hn[(size_t)(C + 4 * cb + 1) * HW + pix] = cur[(size_t)(4 * cb + 1) * HW + pix];
        hn[(size_t)(C + 4 * cb + 2) * HW + pix] = cur[(size_t)(4 * cb + 2) * HW + pix];
        hn[(size_t)(C + 4 * cb + 3) * HW + pix] = cur[(size_t)(4 * cb + 3) * HW + pix];
    }
    hn[(size_t)128 * HW + pix] = fx;
    hn[(size_t)129 * HW + pix] = fy;
}

// ---------------------------------------------------------------------------
// Direct 3x3 conv, pad 1, NCHW fp32, FFMA2 inner loop.
// NOW: double-buffered smem, ONE __syncthreads per ci-chunk (8 channels) so
// the LDG phase of chunk c+1 overlaps (across warps) with compute of chunk c.
// Tile loader is div/mod-free (pure adds + predicates).
// smem: 2 x (8x18x34 in + 8x9x16 w) = 48,384 B dynamic -> 4 blocks/SM.
// ---------------------------------------------------------------------------
#define CONV_CI       8
#define CONV_IN_FL    (CONV_CI * 18 * 34)            // 4896
#define CONV_W_FL     (CONV_CI * 9 * 16)             // 1152
#define CONV_SMEM_B   ((CONV_IN_FL + CONV_W_FL) * 2 * 4)  // 48,384

template<bool RELU>
__global__ __launch_bounds__(128) void conv3x3_k(
    const float* __restrict__ in, const float* __restrict__ wt,
    const float* __restrict__ bias, float* __restrict__ out,
    int Cin, int Cout)
{
    extern __shared__ float csm[];
    // buffer b: input at csm + b*CONV_IN_FL, weights at csm + 2*CONV_IN_FL + b*CONV_W_FL
    float* s_in_base = csm;
    float* s_w_base  = csm + 2 * CONV_IN_FL;

    const int tx = threadIdx.x;              // 0..31
    const int ty = threadIdx.y;              // 0..3
    const int tid = ty * 32 + tx;
    const int x0 = blockIdx.x * 32;
    const int y0 = (blockIdx.y % 6) * 16;
    const int n  = blockIdx.y / 6;
    const int co0 = blockIdx.z * 16;
    const float* inN = in + (size_t)n * Cin * HW;

    const int NC = (Cin + CONV_CI - 1) / CONV_CI;

    // ---- div/mod-free chunk loader ----
    auto load_chunk = [&](int c0, float* s_in, float* s_w) {
        #pragma unroll
        for (int ci = 0; ci < CONV_CI; ci++) {
            int c = c0 + ci;
            bool cv = (c < Cin);
            const float* g = inN + (size_t)c * HW;
            #pragma unroll
            for (int rr = 0; rr < 5; rr++) {
                int iy = ty + 4 * rr;                 // 0..19
                if (iy < 18) {
                    int gy = y0 + iy - 1;
                    bool rowv = cv && ((unsigned)gy < (unsigned)H);
                    const float* gr = g + gy * W;
                    float* sr = s_in + (ci * 18 + iy) * 34;
                    {
                        int gx = x0 + tx - 1;
                        sr[tx] = (rowv && (unsigned)gx < (unsigned)W) ? gr[gx] : 0.f;
                    }
                    if (tx < 2) {
                        int gx = x0 + 32 + tx - 1;
                        sr[32 + tx] = (rowv && (unsigned)gx < (unsigned)W) ? gr[gx] : 0.f;
                    }
                }
            }
        }
        // weights: 1152 floats, 9 per thread; dest-linear index
        #pragma unroll
        for (int j = 0; j < 9; j++) {
            int i = tid + j * 128;                    // 0..1151
            int ci = i / 144;
            int rem = i - ci * 144;
            int k = rem >> 4;                         // /16
            int co = rem & 15;
            int c = c0 + ci;
            s_w[i] = (c < Cin) ? wt[((size_t)(co0 + co) * Cin + c) * 9 + k] : 0.f;
        }
    };

    unsigned long long acc[4][8];
    #pragma unroll
    for (int r = 0; r < 4; r++)
        #pragma unroll
        for (int o = 0; o < 8; o++) acc[r][o] = 0ull;

    load_chunk(0, s_in_base, s_w_base);
    __syncthreads();

    for (int c = 0; c < NC; c++) {
        float* s_in = s_in_base + (c & 1) * CONV_IN_FL;
        float* s_w  = s_w_base  + (c & 1) * CONV_W_FL;
        if (c + 1 < NC)
            load_chunk((c + 1) * CONV_CI,
                       s_in_base + ((c + 1) & 1) * CONV_IN_FL,
                       s_w_base  + ((c + 1) & 1) * CONV_W_FL);

        #pragma unroll
        for (int ci = 0; ci < CONV_CI; ci++) {
            #pragma unroll
            for (int k = 0; k < 9; k++) {
                const int ky = k / 3, kx = k % 3;
                unsigned long long vv[4];
                #pragma unroll
                for (int r = 0; r < 4; r++) {
                    float v = s_in[(ci * 18 + ty + 4 * r + ky) * 34 + tx + kx];
                    vv[r] = pack2(v, v);
                }
                #pragma unroll
                for (int o = 0; o < 8; o++) {
                    unsigned long long wp =
                        *(const unsigned long long*)&s_w[(ci * 9 + k) * 16 + 2 * o];
                    #pragma unroll
                    for (int r = 0; r < 4; r++)
                        ffma2(acc[r][o], vv[r], wp);
                }
            }
        }
        __syncthreads();
    }

    #pragma unroll
    for (int o = 0; o < 8; o++) {
        float b0 = bias[co0 + 2 * o];
        float b1 = bias[co0 + 2 * o + 1];
        #pragma unroll
        for (int r = 0; r < 4; r++) {
            float2 a = unpack2(acc[r][o]);
            a.x += b0; a.y += b1;
            if (RELU) {
                a.x = (a.x >= 0.f) ? a.x : NEG * a.x;
                a.y = (a.y >= 0.f) ? a.y : NEG * a.y;
            }
            size_t base = (size_t)(y0 + ty + 4 * r) * W + (x0 + tx);
            out[((size_t)n * Cout + co0 + 2 * o)     * HW + base] = a.x;
            out[((size_t)n * Cout + co0 + 2 * o + 1) * HW + base] = a.y;
        }
    }
}

// ---------------------------------------------------------------------------
// Deform stage A: offsets + bilinear sampling -> g_samp[n][576][HW].
// NHWC source: one LDG.128 per bilinear corner covers the 4-channel group.
// ---------------------------------------------------------------------------
__global__ __launch_bounds__(128) void sample_k(
    const float4* __restrict__ xt4, const float* __restrict__ fb,
    const float* __restrict__ ff, const float* __restrict__ o4,
    float* __restrict__ samp)
{
    const int pix = blockIdx.x * 128 + threadIdx.x;
    const int dg  = blockIdx.y;
    const int n   = blockIdx.z;
    const int y   = pix / W;
    const int xx  = pix % W;

    int src_t;
    const float* flow;
    if (n < 6) { src_t = n + 1; flow = fb + (size_t)n * 2 * HW; }
    else       { src_t = n - 6; flow = ff + (size_t)(n - 6) * 2 * HW; }
    const float4* srct = xt4 + (size_t)src_t * HW * (C / 4) + dg;
    const float* o4n   = o4 + (size_t)n * COUT4 * HW + pix;
    float*       sampn = samp + (size_t)n * 576 * HW + (size_t)dg * 36 * HW + pix;

    const float fx = flow[pix];
    const float fy = flow[HW + pix];

    #pragma unroll
    for (int kk = 0; kk < 9; kk++) {
        float t0 = o4n[(size_t)(dg * 18 + kk * 2)     * HW];
        float t1 = o4n[(size_t)(dg * 18 + kk * 2 + 1) * HW];
        float tm = o4n[(size_t)(288 + dg * 9 + kk)    * HW];
        float m  = fast_sigmoid(tm);
        float py = 10.f * fast_tanh(t0) + fy + (float)(y  - 1 + kk / 3);
        float px = 10.f * fast_tanh(t1) + fx + (float)(xx - 1 + kk % 3);

        float y0f = floorf(py), x0f = floorf(px);
        int iy0 = (int)y0f, ix0 = (int)x0f;
        float wy = py - y0f, wx = px - x0f;
        bool vy0 = (iy0 >= 0) && (iy0 < H);
        bool vy1 = (iy0 + 1 >= 0) && (iy0 + 1 < H);
        bool vx0 = (ix0 >= 0) && (ix0 < W);
        bool vx1 = (ix0 + 1 >= 0) && (ix0 + 1 < W);
        int yc0 = min(max(iy0, 0), H - 1),     yc1 = min(max(iy0 + 1, 0), H - 1);
        int xc0 = min(max(ix0, 0), W - 1),     xc1 = min(max(ix0 + 1, 0), W - 1);
        float w00 = (1.f - wy) * (1.f - wx) * ((vy0 && vx0) ? m : 0.f);
        float w01 = (1.f - wy) * wx          * ((vy0 && vx1) ? m : 0.f);
        float w10 = wy * (1.f - wx)          * ((vy1 && vx0) ? m : 0.f);
        float w11 = wy * wx                  * ((vy1 && vx1) ? m : 0.f);
        int i00 = yc0 * W + xc0, i01 = yc0 * W + xc1;
        int i10 = yc1 * W + xc0, i11 = yc1 * W + xc1;

        float4 a = srct[(size_t)i00 * (C / 4)];
        float4 b = srct[(size_t)i01 * (C / 4)];
        float4 c = srct[(size_t)i10 * (C / 4)];
        float4 d = srct[(size_t)i11 * (C / 4)];
        float4 v;
        v.x = w00 * a.x + w01 * b.x + w10 * c.x + w11 * d.x;
        v.y = w00 * a.y + w01 * b.y + w10 * c.y + w11 * d.y;
        v.z = w00 * a.z + w01 * b.z + w10 * c.z + w11 * d.z;
        v.w = w00 * a.w + w01 * b.w + w10 * c.w + w11 * d.w;

        sampn[(size_t)(0 * 9 + kk) * HW] = v.x;
        sampn[(size_t)(1 * 9 + kk) * HW] = v.y;
        sampn[(size_t)(2 * 9 + kk) * HW] = v.z;
        sampn[(size_t)(3 * 9 + kk) * HW] = v.w;
    }
}

// ---------------------------------------------------------------------------
// Deform stage B: out[n][64][HW] = W[64][576] @ samp[n][576][HW] + bias.
// ---------------------------------------------------------------------------
#define GEMM_SMEM_FLOATS (64 * 128)
#define GEMM_SMEM_BYTES  (GEMM_SMEM_FLOATS * 4 + 64 * 66 * 8)   // 66,560 B

__global__ __launch_bounds__(128) void gemm_k(
    const float* __restrict__ samp, const float* __restrict__ dw,
    const float* __restrict__ db, float* __restrict__ out)
{
    extern __shared__ float sm[];
    float*  s_s  = sm;                               // [64][128]  32 KB
    float2* s_w2 = (float2*)(sm + GEMM_SMEM_FLOATS); // [64][66]   33.8 KB

    const int tid = threadIdx.x;
    const int pxb = blockIdx.x * 128;
    const int n   = blockIdx.y;
    const float* sampn = samp + (size_t)n * 576 * HW;

    const int pg = tid & 15;    // pixel group: 8 px = 4 f32x2 pairs
    const int og = tid >> 4;    // cout group: 8 couts

    unsigned long long acc[8][4];
    #pragma unroll
    for (int o = 0; o < 8; o++)
        #pragma unroll
        for (int p = 0; p < 4; p++) acc[o][p] = 0ull;

    for (int k0 = 0; k0 < 576; k0 += 64) {
        for (int i = tid; i < 64 * 32; i += 128) {
            int r = i >> 5, c4 = i & 31;
            *(float4*)&s_s[r * 128 + c4 * 4] =
                *(const float4*)&sampn[(size_t)(k0 + r) * HW + pxb + c4 * 4];
        }
        for (int i = tid; i < 64 * 64; i += 128) {
            int co = i >> 6, kk = i & 63;
            float w = dw[(size_t)co * 576 + k0 + kk];
            s_w2[kk * 66 + co] = make_float2(w, w);
        }
        __syncthreads();

        #pragma unroll 2
        for (int kk = 0; kk < 64; kk++) {
            ulonglong2 p0 = *(const ulonglong2*)&s_s[kk * 128 + pg * 8];
            ulonglong2 p1 = *(const ulonglong2*)&s_s[kk * 128 + pg * 8 + 4];
            unsigned long long wq[8];
            #pragma unroll
            for (int j = 0; j < 4; j++) {
                ulonglong2 wv = *(const ulonglong2*)&s_w2[kk * 66 + og * 8 + 2 * j];
                wq[2 * j]     = wv.x;
                wq[2 * j + 1] = wv.y;
            }
            #pragma unroll
            for (int o = 0; o < 8; o++) {
                ffma2(acc[o][0], wq[o], p0.x);
                ffma2(acc[o][1], wq[o], p0.y);
                ffma2(acc[o][2], wq[o], p1.x);
                ffma2(acc[o][3], wq[o], p1.y);
            }
        }
        __syncthreads();
    }

    float* outn = (n < 6) ? out + (size_t)n * C * HW
                          : out + (size_t)(7 + (n - 6) + 1) * C * HW;
    #pragma unroll
    for (int o = 0; o < 8; o++) {
        int co = og * 8 + o;
        float bv = db[co];
        float2 a0 = unpack2(acc[o][0]);
        float2 a1 = unpack2(acc[o][1]);
        float2 a2 = unpack2(acc[o][2]);
        float2 a3 = unpack2(acc[o][3]);
        float4 v0 = make_float4(a0.x + bv, a0.y + bv, a1.x + bv, a1.y + bv);
        float4 v1 = make_float4(a2.x + bv, a2.y + bv, a3.x + bv, a3.y + bv);
        size_t base = (size_t)co * HW + pxb + pg * 8;
        *(float4*)&outn[base]     = v0;
        *(float4*)&outn[base + 4] = v1;
    }
}

// ---------------------------------------------------------------------------
// Launch
// ---------------------------------------------------------------------------
extern "C" void kernel_launch(void* const* d_in, const int* in_sizes, int n_in,
                              void* d_out, int out_size)
{
    const float* x  = (const float*)d_in[0];
    const float* fb = (const float*)d_in[1];
    const float* ff = (const float*)d_in[2];
    const float* w1 = (const float*)d_in[3];  const float* b1 = (const float*)d_in[4];
    const float* w2 = (const float*)d_in[5];  const float* b2 = (const float*)d_in[6];
    const float* w3 = (const float*)d_in[7];  const float* b3 = (const float*)d_in[8];
    const float* w4 = (const float*)d_in[9];  const float* b4 = (const float*)d_in[10];
    const float* dw = (const float*)d_in[11]; const float* db = (const float*)d_in[12];
    float* out = (float*)d_out;

    float *h0, *h1, *h2, *o4, *sp, *xt;
    cudaGetSymbolAddress((void**)&h0, g_h0);
    cudaGetSymbolAddress((void**)&h1, g_h1);
    cudaGetSymbolAddress((void**)&h2, g_h2);
    cudaGetSymbolAddress((void**)&o4, g_o4);
    cudaGetSymbolAddress((void**)&sp, g_samp);
    cudaGetSymbolAddress((void**)&xt, g_xt);

    {   // Zero only frames 6..7 (bwd[6] and fwd[0])
        int n4 = 2 * C * HW / 4;
        zero_k<<<(n4 + 255) / 256, 256>>>((float4*)(out + (size_t)6 * C * HW), n4);
    }
    nhwc_k<<<(T * HW + 127) / 128, 128>>>(x, (float4*)xt);
    warp_concat_k<<<(NB * HW + 255) / 256, 256>>>(x, (const float4*)xt, fb, ff, h0);

    cudaFuncSetAttribute(conv3x3_k<true>,
                         cudaFuncAttributeMaxDynamicSharedMemorySize, CONV_SMEM_B);
    cudaFuncSetAttribute(conv3x3_k<false>,
                         cudaFuncAttributeMaxDynamicSharedMemorySize, CONV_SMEM_B);

    dim3 cb(32, 4);
    conv3x3_k<true ><<<dim3(3, 72, 4),  cb, CONV_SMEM_B>>>(h0, w1, b1, h1, CIN1, C);
    conv3x3_k<true ><<<dim3(3, 72, 4),  cb, CONV_SMEM_B>>>(h1, w2, b2, h2, C,    C);
    conv3x3_k<true ><<<dim3(3, 72, 4),  cb, CONV_SMEM_B>>>(h2, w3, b3, h1, C,    C);
    conv3x3_k<false><<<dim3(3, 72, 27), cb, CONV_SMEM_B>>>(h1, w4, b4, o4, C, COUT4);

    sample_k<<<dim3(72, 16, NB), 128>>>((const float4*)xt, fb, ff, o4, sp);

    cudaFuncSetAttribute(gemm_k, cudaFuncAttributeMaxDynamicSharedMemorySize,
                         GEMM_SMEM_BYTES);
    gemm_k<<<dim3(72, NB), 128, GEMM_SMEM_BYTES>>>(sp, dw, db, out);
}

// round 7
// speedup vs baseline: 1.6313x; 1.6313x over previous
#include <cuda_runtime.h>
#include <cuda_bf16.h>
#include <math.h>

// Problem constants
#define H     96
#define W     96
#define HW    9216           // H*W
#define C     64
#define T     7
#define NB    12             // 6 backward + 6 forward frame pairs
#define CIN1  130            // warped(64) + x_cur(64) + flow(2)
#define COUT4 432            // 3 * 9 * 16
#define NEG   0.1f
#define PW    101            // padded width/height (pad=2 each side, +1 slack)
#define PPIX  (PW * PW)      // 10201 padded pixels

// ---------------------------------------------------------------------------
// Packed fp32x2 helpers (sm_100a FFMA2 path — 2 fp32 FMAs per issue slot)
// ---------------------------------------------------------------------------
__device__ __forceinline__ void ffma2(unsigned long long& d,
                                      unsigned long long a,
                                      unsigned long long b) {
    asm("fma.rn.f32x2 %0, %1, %2, %0;" : "+l"(d) : "l"(a), "l"(b));
}
__device__ __forceinline__ unsigned long long pack2(float lo, float hi) {
    unsigned long long r;
    asm("mov.b64 %0, {%1, %2};" : "=l"(r) : "f"(lo), "f"(hi));
    return r;
}
__device__ __forceinline__ float2 unpack2(unsigned long long v) {
    float2 r;
    asm("mov.b64 {%0, %1}, %2;" : "=f"(r.x), "=f"(r.y) : "l"(v));
    return r;
}
__device__ __forceinline__ float fast_rcp(float x) {
    float r;
    asm("rcp.approx.f32 %0, %1;" : "=f"(r) : "f"(x));
    return r;
}
// Clamp-free tanh / sigmoid: MUFU EX2 + MUFU RCP, saturates correctly at +/-inf.
__device__ __forceinline__ float fast_tanh(float x) {
    float e = __expf(2.f * x);              // FMUL + MUFU.EX2
    return fmaf(-2.f, fast_rcp(e + 1.f), 1.f);
}
__device__ __forceinline__ float fast_sigmoid(float x) {
    return fast_rcp(1.f + __expf(-x));
}

// ---------------------------------------------------------------------------
// Scratch buffers (device globals -- no allocation allowed in kernel_launch)
// ---------------------------------------------------------------------------
__device__ float g_h0[NB * CIN1 * HW];      // concat input
__device__ float g_h1[NB * C * HW];         // conv1 out / conv3 out
__device__ float g_h2[NB * C * HW];         // conv2 out
__device__ float g_o4[NB * COUT4 * HW];     // conv4 out
__device__ float g_samp[NB * 144 * HW * 4]; // deform samples [n][tap][pix][4ch]
__device__ float g_xp[T * PPIX * C];        // zero-padded NHWC x (18.3 MB)

// ---------------------------------------------------------------------------
// Zero only the two frames deform never writes (bwd[6], fwd[0])
// ---------------------------------------------------------------------------
__global__ void zero_k(float4* __restrict__ p, int n4) {
    int i = blockIdx.x * blockDim.x + threadIdx.x;
    if (i < n4) p[i] = make_float4(0.f, 0.f, 0.f, 0.f);
}

// ---------------------------------------------------------------------------
// Build zero-padded NHWC image: g_xp[t][(y+2)*101+(x+2)][64].
// Interior = transpose of NCHW x; ring (2 px + slack) = zeros.
// ---------------------------------------------------------------------------
__global__ void pad_k(const float* __restrict__ x, float4* __restrict__ xp4) {
    int p = blockIdx.x * blockDim.x + threadIdx.x;
    if (p >= T * PPIX) return;
    int t = p / PPIX, rem = p % PPIX;
    int yy = rem / PW - 2, xx = rem % PW - 2;
    float4* dst = xp4 + (size_t)p * (C / 4);
    if ((unsigned)yy < (unsigned)H && (unsigned)xx < (unsigned)W) {
        const float* xn = x + (size_t)t * C * HW + yy * W + xx;
        #pragma unroll
        for (int cb = 0; cb < C / 4; cb++) {
            float4 v;
            v.x = xn[(size_t)(4 * cb + 0) * HW];
            v.y = xn[(size_t)(4 * cb + 1) * HW];
            v.z = xn[(size_t)(4 * cb + 2) * HW];
            v.w = xn[(size_t)(4 * cb + 3) * HW];
            dst[cb] = v;
        }
    } else {
        float4 z = make_float4(0.f, 0.f, 0.f, 0.f);
        #pragma unroll
        for (int cb = 0; cb < C / 4; cb++) dst[cb] = z;
    }
}

// ---------------------------------------------------------------------------
// Stage 1: flow-warp x_src via padded image (no validity logic) + concat.
// ---------------------------------------------------------------------------
__global__ void warp_concat_k(const float* __restrict__ x,
                              const float4* __restrict__ xp4,
                              const float* __restrict__ fb,
                              const float* __restrict__ ff,
                              float* __restrict__ h0) {
    int p = blockIdx.x * blockDim.x + threadIdx.x;
    if (p >= NB * HW) return;
    int n = p / HW, pix = p % HW;
    int yy = pix / W, xx = pix % W;

    int src_t, cur_t;
    const float* flow;
    if (n < 6) { src_t = n + 1; cur_t = n;     flow = fb + (size_t)n * 2 * HW; }
    else       { int m = n - 6; src_t = m; cur_t = m + 1; flow = ff + (size_t)m * 2 * HW; }

    float fx = flow[pix];
    float fy = flow[HW + pix];
    float px = fminf(fmaxf((float)xx + fx, -2.f), (float)(W + 1));
    float py = fminf(fmaxf((float)yy + fy, -2.f), (float)(H + 1));

    int iy0 = __float2int_rd(py), ix0 = __float2int_rd(px);
    float wy = py - (float)iy0, wx = px - (float)ix0;
    float w00 = (1.f - wy) * (1.f - wx);
    float w01 = (1.f - wy) * wx;
    float w10 = wy * (1.f - wx);
    float w11 = wy * wx;

    int base = (iy0 + 2) * PW + (ix0 + 2);
    const float4* sp = xp4 + (size_t)src_t * PPIX * (C / 4);
    const float4* s00 = sp + (size_t)base * (C / 4);
    const float4* s01 = sp + (size_t)(base + 1) * (C / 4);
    const float4* s10 = sp + (size_t)(base + PW) * (C / 4);
    const float4* s11 = sp + (size_t)(base + PW + 1) * (C / 4);
    const float* cur = x + (size_t)cur_t * C * HW;
    float* hn = h0 + (size_t)n * CIN1 * HW;

    #pragma unroll 4
    for (int cb = 0; cb < C / 4; cb++) {
        float4 a = s00[cb], b = s01[cb], c = s10[cb], d = s11[cb];
        float4 v;
        v.x = w00 * a.x + w01 * b.x + w10 * c.x + w11 * d.x;
        v.y = w00 * a.y + w01 * b.y + w10 * c.y + w11 * d.y;
        v.z = w00 * a.z + w01 * b.z + w10 * c.z + w11 * d.z;
        v.w = w00 * a.w + w01 * b.w + w10 * c.w + w11 * d.w;
        hn[(size_t)(4 * cb + 0) * HW + pix] = v.x;
        hn[(size_t)(4 * cb + 1) * HW + pix] = v.y;
        hn[(size_t)(4 * cb + 2) * HW + pix] = v.z;
        hn[(size_t)(4 * cb + 3) * HW + pix] = v.w;
        hn[(size_t)(C + 4 * cb + 0) * HW + pix] = cur[(size_t)(4 * cb + 0) * HW + pix];
        hn[(size_t)(C + 4 * cb + 1) * HW + pix] = cur[(size_t)(4 * cb + 1) * HW + pix];
        hn[(size_t)(C + 4 * cb + 2) * HW + pix] = cur[(size_t)(4 * cb + 2) * HW + pix];
        hn[(size_t)(C + 4 * cb + 3) * HW + pix] = cur[(size_t)(4 * cb + 3) * HW + pix];
    }
    hn[(size_t)128 * HW + pix] = fx;
    hn[(size_t)129 * HW + pix] = fy;
}

// ---------------------------------------------------------------------------
// Direct 3x3 conv — ROUND-4 VERSION (known good: conv1 = 258us).
// ---------------------------------------------------------------------------
template<bool RELU>
__global__ __launch_bounds__(128) void conv3x3_k(
    const float* __restrict__ in, const float* __restrict__ wt,
    const float* __restrict__ bias, float* __restrict__ out,
    int Cin, int Cout)
{
    __shared__ float s_in[16][18][34];   // [ci][y][x]   39.2 KB
    __shared__ float s_w[16][9][16];     // [ci][k][co]   9.2 KB

    const int tx = threadIdx.x;
    const int ty = threadIdx.y;
    const int tid = ty * 32 + tx;
    const int x0 = blockIdx.x * 32;
    const int y0 = (blockIdx.y % 6) * 16;
    const int n  = blockIdx.y / 6;
    const int co0 = blockIdx.z * 16;
    const float* inN = in + (size_t)n * Cin * HW;

    unsigned long long acc[4][8];
    #pragma unroll
    for (int r = 0; r < 4; r++)
        #pragma unroll
        for (int o = 0; o < 8; o++) acc[r][o] = 0ull;

    for (int c0 = 0; c0 < Cin; c0 += 16) {
        for (int i = tid; i < 16 * 18 * 34; i += 128) {
            int ci  = i / (18 * 34);
            int rem = i % (18 * 34);
            int iy = rem / 34, ix = rem % 34;
            int gy = y0 + iy - 1, gx = x0 + ix - 1;
            int c = c0 + ci;
            float v = 0.f;
            if (c < Cin && (unsigned)gy < (unsigned)H && (unsigned)gx < (unsigned)W)
                v = inN[(size_t)c * HW + gy * W + gx];
            s_in[ci][iy][ix] = v;
        }
        for (int i = tid; i < 16 * 16 * 9; i += 128) {
            int co = i / 144, rem = i % 144;
            int ci = rem / 9, k = rem % 9;
            int c = c0 + ci;
            s_w[ci][k][co] = (c < Cin) ? wt[((size_t)(co0 + co) * Cin + c) * 9 + k] : 0.f;
        }
        __syncthreads();

        for (int ci = 0; ci < 16; ci++) {
            #pragma unroll
            for (int k = 0; k < 9; k++) {
                const int ky = k / 3, kx = k % 3;
                unsigned long long vv[4];
                #pragma unroll
                for (int r = 0; r < 4; r++) {
                    float v = s_in[ci][ty + 4 * r + ky][tx + kx];
                    vv[r] = pack2(v, v);
                }
                #pragma unroll
                for (int o = 0; o < 8; o++) {
                    unsigned long long wp =
                        *(const unsigned long long*)&s_w[ci][k][2 * o];
                    #pragma unroll
                    for (int r = 0; r < 4; r++)
                        ffma2(acc[r][o], vv[r], wp);
                }
            }
        }
        __syncthreads();
    }

    #pragma unroll
    for (int o = 0; o < 8; o++) {
        float b0 = bias[co0 + 2 * o];
        float b1 = bias[co0 + 2 * o + 1];
        #pragma unroll
        for (int r = 0; r < 4; r++) {
            float2 a = unpack2(acc[r][o]);
            a.x += b0; a.y += b1;
            if (RELU) {
                a.x = (a.x >= 0.f) ? a.x : NEG * a.x;
                a.y = (a.y >= 0.f) ? a.y : NEG * a.y;
            }
            size_t base = (size_t)(y0 + ty + 4 * r) * W + (x0 + tx);
            out[((size_t)n * Cout + co0 + 2 * o)     * HW + base] = a.x;
            out[((size_t)n * Cout + co0 + 2 * o + 1) * HW + base] = a.y;
        }
    }
}

// ---------------------------------------------------------------------------
// Deform stage A: offsets + bilinear sampling from the PADDED image.
// No validity logic (pad ring of zeros reproduces it); clamp-free tanh/sigmoid;
// one STG.128 per tap into [n][tap][pix][4] layout; FFMA2 bilinear blend.
// ---------------------------------------------------------------------------
__global__ __launch_bounds__(128) void sample_k(
    const float4* __restrict__ xp4, const float* __restrict__ fb,
    const float* __restrict__ ff, const float* __restrict__ o4,
    float4* __restrict__ samp)
{
    const int pix = blockIdx.x * 128 + threadIdx.x;
    const int dg  = blockIdx.y;
    const int n   = blockIdx.z;
    const int y   = pix / W;
    const int xx  = pix % W;

    int src_t;
    const float* flow;
    if (n < 6) { src_t = n + 1; flow = fb + (size_t)n * 2 * HW; }
    else       { src_t = n - 6; flow = ff + (size_t)(n - 6) * 2 * HW; }
    const float4* srcp = xp4 + (size_t)src_t * PPIX * (C / 4) + dg;
    const float* o4n   = o4 + (size_t)n * COUT4 * HW + pix;
    float4*      sampn = samp + ((size_t)n * 144 + (size_t)dg * 9) * HW + pix;

    const float fx = flow[pix];
    const float fy = flow[HW + pix];

    #pragma unroll
    for (int kk = 0; kk < 9; kk++) {
        float t0 = o4n[(size_t)(dg * 18 + kk * 2)     * HW];
        float t1 = o4n[(size_t)(dg * 18 + kk * 2 + 1) * HW];
        float tm = o4n[(size_t)(288 + dg * 9 + kk)    * HW];
        float m  = fast_sigmoid(tm);
        float py = 10.f * fast_tanh(t0) + fy + (float)(y  - 1 + kk / 3);
        float px = 10.f * fast_tanh(t1) + fx + (float)(xx - 1 + kk % 3);
        py = fminf(fmaxf(py, -2.f), (float)(H + 1));
        px = fminf(fmaxf(px, -2.f), (float)(W + 1));

        int iy0 = __float2int_rd(py), ix0 = __float2int_rd(px);
        float wy = py - (float)iy0, wx = px - (float)ix0;
        // fold mask into y-weights
        float wy1m = m * wy;
        float wy0m = m - wy1m;
        float wx0 = 1.f - wx;
        float w00 = wy0m * wx0, w01 = wy0m * wx;
        float w10 = wy1m * wx0, w11 = wy1m * wx;

        int base = (iy0 + 2) * PW + (ix0 + 2);
        ulonglong2 a = *(const ulonglong2*)(srcp + (size_t)base * (C / 4));
        ulonglong2 b = *(const ulonglong2*)(srcp + (size_t)(base + 1) * (C / 4));
        ulonglong2 c = *(const ulonglong2*)(srcp + (size_t)(base + PW) * (C / 4));
        ulonglong2 d = *(const ulonglong2*)(srcp + (size_t)(base + PW + 1) * (C / 4));

        unsigned long long w00p = pack2(w00, w00), w01p = pack2(w01, w01);
        unsigned long long w10p = pack2(w10, w10), w11p = pack2(w11, w11);
        unsigned long long v0 = 0ull, v1 = 0ull;
        ffma2(v0, w00p, a.x); ffma2(v1, w00p, a.y);
        ffma2(v0, w01p, b.x); ffma2(v1, w01p, b.y);
        ffma2(v0, w10p, c.x); ffma2(v1, w10p, c.y);
        ffma2(v0, w11p, d.x); ffma2(v1, w11p, d.y);

        ulonglong2 outv; outv.x = v0; outv.y = v1;
        *(ulonglong2*)&sampn[(size_t)kk * HW] = outv;
    }
}

// ---------------------------------------------------------------------------
// Deform stage B: out[n][64co][HW] = W' @ samp + bias, K=576 in permuted order
// j = tap*4+cg  (orig k = (dg*4+cg)*9+kk). Weight loader applies the perm.
// s_s row stride 132 floats kills the scatter-store bank conflict.
// ---------------------------------------------------------------------------
#define GEMM_SS_FL   (64 * 132)
#define GEMM_SMEM_BYTES  (GEMM_SS_FL * 4 + 64 * 66 * 8)   // 67,584 B

__global__ __launch_bounds__(128) void gemm_k(
    const float4* __restrict__ samp, const float* __restrict__ dw,
    const float* __restrict__ db, float* __restrict__ out)
{
    extern __shared__ float sm[];
    float*  s_s  = sm;                          // [64][132]
    float2* s_w2 = (float2*)(sm + GEMM_SS_FL);  // [64][66] dup pairs

    const int tid = threadIdx.x;
    const int pxb = blockIdx.x * 128;
    const int n   = blockIdx.y;
    const float4* sampn = samp + (size_t)n * 144 * HW;

    const int pg = tid & 15;    // pixel group: 8 px = 4 f32x2 pairs
    const int og = tid >> 4;    // cout group: 8 couts

    unsigned long long acc[8][4];
    #pragma unroll
    for (int o = 0; o < 8; o++)
        #pragma unroll
        for (int p = 0; p < 4; p++) acc[o][p] = 0ull;

    for (int k0 = 0; k0 < 576; k0 += 64) {
        const int tap0 = k0 >> 2;                 // 16 taps per chunk
        // samp chunk: thread tid loads float4 (tap, px=tid), scatters 4 rows
        #pragma unroll
        for (int l = 0; l < 16; l++) {
            float4 v = sampn[(size_t)(tap0 + l) * HW + pxb + tid];
            s_s[(l * 4 + 0) * 132 + tid] = v.x;
            s_s[(l * 4 + 1) * 132 + tid] = v.y;
            s_s[(l * 4 + 2) * 132 + tid] = v.z;
            s_s[(l * 4 + 3) * 132 + tid] = v.w;
        }
        // weights with permutation j -> k
        for (int i = tid; i < 64 * 64; i += 128) {
            int co = i >> 6, jj = i & 63;
            int j = k0 + jj;
            int t = j >> 2, cg = j & 3;
            int dg = t / 9, kkid = t - 9 * dg;
            int k = (dg * 4 + cg) * 9 + kkid;
            float w = dw[(size_t)co * 576 + k];
            s_w2[jj * 66 + co] = make_float2(w, w);
        }
        __syncthreads();

        #pragma unroll 2
        for (int kk = 0; kk < 64; kk++) {
            ulonglong2 p0 = *(const ulonglong2*)&s_s[kk * 132 + pg * 8];
            ulonglong2 p1 = *(const ulonglong2*)&s_s[kk * 132 + pg * 8 + 4];
            unsigned long long wq[8];
            #pragma unroll
            for (int j = 0; j < 4; j++) {
                ulonglong2 wv = *(const ulonglong2*)&s_w2[kk * 66 + og * 8 + 2 * j];
                wq[2 * j]     = wv.x;
                wq[2 * j + 1] = wv.y;
            }
            #pragma unroll
            for (int o = 0; o < 8; o++) {
                ffma2(acc[o][0], wq[o], p0.x);
                ffma2(acc[o][1], wq[o], p0.y);
                ffma2(acc[o][2], wq[o], p1.x);
                ffma2(acc[o][3], wq[o], p1.y);
            }
        }
        __syncthreads();
    }

    float* outn = (n < 6) ? out + (size_t)n * C * HW
                          : out + (size_t)(7 + (n - 6) + 1) * C * HW;
    #pragma unroll
    for (int o = 0; o < 8; o++) {
        int co = og * 8 + o;
        float bv = db[co];
        float2 a0 = unpack2(acc[o][0]);
        float2 a1 = unpack2(acc[o][1]);
        float2 a2 = unpack2(acc[o][2]);
        float2 a3 = unpack2(acc[o][3]);
        float4 v0 = make_float4(a0.x + bv, a0.y + bv, a1.x + bv, a1.y + bv);
        float4 v1 = make_float4(a2.x + bv, a2.y + bv, a3.x + bv, a3.y + bv);
        size_t base = (size_t)co * HW + pxb + pg * 8;
        *(float4*)&outn[base]     = v0;
        *(float4*)&outn[base + 4] = v1;
    }
}

// ---------------------------------------------------------------------------
// Launch
// ---------------------------------------------------------------------------
extern "C" void kernel_launch(void* const* d_in, const int* in_sizes, int n_in,
                              void* d_out, int out_size)
{
    const float* x  = (const float*)d_in[0];
    const float* fb = (const float*)d_in[1];
    const float* ff = (const float*)d_in[2];
    const float* w1 = (const float*)d_in[3];  const float* b1 = (const float*)d_in[4];
    const float* w2 = (const float*)d_in[5];  const float* b2 = (const float*)d_in[6];
    const float* w3 = (const float*)d_in[7];  const float* b3 = (const float*)d_in[8];
    const float* w4 = (const float*)d_in[9];  const float* b4 = (const float*)d_in[10];
    const float* dw = (const float*)d_in[11]; const float* db = (const float*)d_in[12];
    float* out = (float*)d_out;

    float *h0, *h1, *h2, *o4, *sp, *xp;
    cudaGetSymbolAddress((void**)&h0, g_h0);
    cudaGetSymbolAddress((void**)&h1, g_h1);
    cudaGetSymbolAddress((void**)&h2, g_h2);
    cudaGetSymbolAddress((void**)&o4, g_o4);
    cudaGetSymbolAddress((void**)&sp, g_samp);
    cudaGetSymbolAddress((void**)&xp, g_xp);

    {   // Zero only frames 6..7 (bwd[6] and fwd[0])
        int n4 = 2 * C * HW / 4;
        zero_k<<<(n4 + 255) / 256, 256>>>((float4*)(out + (size_t)6 * C * HW), n4);
    }
    pad_k<<<(T * PPIX + 127) / 128, 128>>>(x, (float4*)xp);
    warp_concat_k<<<(NB * HW + 255) / 256, 256>>>(x, (const float4*)xp, fb, ff, h0);

    dim3 cb(32, 4);
    conv3x3_k<true ><<<dim3(3, 72, 4),  cb>>>(h0, w1, b1, h1, CIN1, C);
    conv3x3_k<true ><<<dim3(3, 72, 4),  cb>>>(h1, w2, b2, h2, C,    C);
    conv3x3_k<true ><<<dim3(3, 72, 4),  cb>>>(h2, w3, b3, h1, C,    C);
    conv3x3_k<false><<<dim3(3, 72, 27), cb>>>(h1, w4, b4, o4, C, COUT4);

    sample_k<<<dim3(72, 16, NB), 128>>>((const float4*)xp, fb, ff, o4, (float4*)sp);

    cudaFuncSetAttribute(gemm_k, cudaFuncAttributeMaxDynamicSharedMemorySize,
                         GEMM_SMEM_BYTES);
    gemm_k<<<dim3(72, NB), 128, GEMM_SMEM_BYTES>>>((const float4*)sp, dw, db, out);
}

// round 10
// speedup vs baseline: 2.2506x; 1.3797x over previous
#include <cuda_runtime.h>
#include <cuda_bf16.h>
#include <math.h>
#include <cstdint>

// Problem constants
#define H     96
#define W     96
#define HW    9216           // H*W
#define C     64
#define T     7
#define NB    12             // 6 backward + 6 forward frame pairs
#define CIN1  130            // warped(64) + x_cur(64) + flow(2)
#define COUT4 432            // 3 * 9 * 16
#define NEG   0.1f
#define PW    101            // padded width/height for x (pad=2 + slack)
#define PPIX  (PW * PW)
#define PW2   98             // padded width for h1 (pad=1)
#define PPIX2 (PW2 * PW2)    // 9604

// ---------------------------------------------------------------------------
// Packed fp32x2 helpers
// ---------------------------------------------------------------------------
__device__ __forceinline__ void ffma2(unsigned long long& d,
                                      unsigned long long a,
                                      unsigned long long b) {
    asm("fma.rn.f32x2 %0, %1, %2, %0;" : "+l"(d) : "l"(a), "l"(b));
}
__device__ __forceinline__ unsigned long long pack2(float lo, float hi) {
    unsigned long long r;
    asm("mov.b64 %0, {%1, %2};" : "=l"(r) : "f"(lo), "f"(hi));
    return r;
}
__device__ __forceinline__ float2 unpack2(unsigned long long v) {
    float2 r;
    asm("mov.b64 {%0, %1}, %2;" : "=f"(r.x), "=f"(r.y) : "l"(v));
    return r;
}
__device__ __forceinline__ float fast_rcp(float x) {
    float r;
    asm("rcp.approx.f32 %0, %1;" : "=f"(r) : "f"(x));
    return r;
}
__device__ __forceinline__ float fast_tanh(float x) {
    float e = __expf(2.f * x);
    return fmaf(-2.f, fast_rcp(e + 1.f), 1.f);
}
__device__ __forceinline__ float fast_sigmoid(float x) {
    return fast_rcp(1.f + __expf(-x));
}

// ---------------------------------------------------------------------------
// mma.sync / ldmatrix helpers (legacy tensor-core path, compute_100-safe)
// ---------------------------------------------------------------------------
__device__ __forceinline__ uint32_t smem_u32(const void* p) {
    uint32_t a;
    asm("{ .reg .u64 t; cvta.to.shared.u64 t, %1; cvt.u32.u64 %0, t; }"
        : "=r"(a) : "l"(p));
    return a;
}
#define LDMATRIX_X4(r0, r1, r2, r3, addr) \
    asm volatile("ldmatrix.sync.aligned.m8n8.x4.shared.b16 {%0,%1,%2,%3}, [%4];" \
                 : "=r"(r0), "=r"(r1), "=r"(r2), "=r"(r3) : "r"(addr))
#define MMA_BF16(d, a, b0, b1) \
    asm volatile("mma.sync.aligned.m16n8k16.row.col.f32.bf16.bf16.f32 " \
                 "{%0,%1,%2,%3}, {%4,%5,%6,%7}, {%8,%9}, {%0,%1,%2,%3};" \
                 : "+f"((d)[0]), "+f"((d)[1]), "+f"((d)[2]), "+f"((d)[3]) \
                 : "r"((a)[0]), "r"((a)[1]), "r"((a)[2]), "r"((a)[3]), \
                   "r"(b0), "r"(b1))
#define SWZ128(off) ((off) ^ (((off) >> 3) & 0x70))

// A-stage region: 3 padded rows x 98 px x 64 ci bf16 = 37632 B, round to 37888
#define C4_AREG   37888
#define C4_SMEM   (2 * C4_AREG)     // hi + lo stages (75776 B)
#define WF_ELEMS  (9 * 4 * 2 * 54 * 32)   // per-(shift,kchunk,split,ntile,lane) u64

// ---------------------------------------------------------------------------
// Scratch buffers
// ---------------------------------------------------------------------------
__device__ float g_h0[NB * CIN1 * HW];
__device__ float g_h1[NB * C * HW];
__device__ float g_h2[NB * C * HW];
__device__ float g_o4[NB * COUT4 * HW];
__device__ float g_samp[NB * 144 * HW * 4];
__device__ float g_xp[T * PPIX * C];
__device__ __nv_bfloat16 g_bhi[NB * PPIX2 * C];       // h1 padded NHWC bf16 hi
__device__ __nv_bfloat16 g_blo[NB * PPIX2 * C];       // h1 padded NHWC bf16 lo
__device__ unsigned long long g_wf[WF_ELEMS];         // prepacked W4 B-frags

// ---------------------------------------------------------------------------
__global__ void zero_k(float4* __restrict__ p, int n4) {
    int i = blockIdx.x * blockDim.x + threadIdx.x;
    if (i < n4) p[i] = make_float4(0.f, 0.f, 0.f, 0.f);
}

// x -> zero-padded NHWC (pad=2)
__global__ void pad_k(const float* __restrict__ x, float4* __restrict__ xp4) {
    int p = blockIdx.x * blockDim.x + threadIdx.x;
    if (p >= T * PPIX) return;
    int t = p / PPIX, rem = p % PPIX;
    int yy = rem / PW - 2, xx = rem % PW - 2;
    float4* dst = xp4 + (size_t)p * (C / 4);
    if ((unsigned)yy < (unsigned)H && (unsigned)xx < (unsigned)W) {
        const float* xn = x + (size_t)t * C * HW + yy * W + xx;
        #pragma unroll
        for (int cb = 0; cb < C / 4; cb++) {
            float4 v;
            v.x = xn[(size_t)(4 * cb + 0) * HW];
            v.y = xn[(size_t)(4 * cb + 1) * HW];
            v.z = xn[(size_t)(4 * cb + 2) * HW];
            v.w = xn[(size_t)(4 * cb + 3) * HW];
            dst[cb] = v;
        }
    } else {
        float4 z = make_float4(0.f, 0.f, 0.f, 0.f);
        #pragma unroll
        for (int cb = 0; cb < C / 4; cb++) dst[cb] = z;
    }
}

// ---------------------------------------------------------------------------
// Stage 1: flow-warp + concat
// ---------------------------------------------------------------------------
__global__ void warp_concat_k(const float* __restrict__ x,
                              const float4* __restrict__ xp4,
                              const float* __restrict__ fb,
                              const float* __restrict__ ff,
                              float* __restrict__ h0) {
    int p = blockIdx.x * blockDim.x + threadIdx.x;
    if (p >= NB * HW) return;
    int n = p / HW, pix = p % HW;
    int yy = pix / W, xx = pix % W;

    int src_t, cur_t;
    const float* flow;
    if (n < 6) { src_t = n + 1; cur_t = n;     flow = fb + (size_t)n * 2 * HW; }
    else       { int m = n - 6; src_t = m; cur_t = m + 1; flow = ff + (size_t)m * 2 * HW; }

    float fx = flow[pix];
    float fy = flow[HW + pix];
    float px = fminf(fmaxf((float)xx + fx, -2.f), (float)(W + 1));
    float py = fminf(fmaxf((float)yy + fy, -2.f), (float)(H + 1));

    int iy0 = __float2int_rd(py), ix0 = __float2int_rd(px);
    float wy = py - (float)iy0, wx = px - (float)ix0;
    float w00 = (1.f - wy) * (1.f - wx);
    float w01 = (1.f - wy) * wx;
    float w10 = wy * (1.f - wx);
    float w11 = wy * wx;

    int base = (iy0 + 2) * PW + (ix0 + 2);
    const float4* sp = xp4 + (size_t)src_t * PPIX * (C / 4);
    const float4* s00 = sp + (size_t)base * (C / 4);
    const float4* s01 = sp + (size_t)(base + 1) * (C / 4);
    const float4* s10 = sp + (size_t)(base + PW) * (C / 4);
    const float4* s11 = sp + (size_t)(base + PW + 1) * (C / 4);
    const float* cur = x + (size_t)cur_t * C * HW;
    float* hn = h0 + (size_t)n * CIN1 * HW;

    #pragma unroll 4
    for (int cb = 0; cb < C / 4; cb++) {
        float4 a = s00[cb], b = s01[cb], c = s10[cb], d = s11[cb];
        float4 v;
        v.x = w00 * a.x + w01 * b.x + w10 * c.x + w11 * d.x;
        v.y = w00 * a.y + w01 * b.y + w10 * c.y + w11 * d.y;
        v.z = w00 * a.z + w01 * b.z + w10 * c.z + w11 * d.z;
        v.w = w00 * a.w + w01 * b.w + w10 * c.w + w11 * d.w;
        hn[(size_t)(4 * cb + 0) * HW + pix] = v.x;
        hn[(size_t)(4 * cb + 1) * HW + pix] = v.y;
        hn[(size_t)(4 * cb + 2) * HW + pix] = v.z;
        hn[(size_t)(4 * cb + 3) * HW + pix] = v.w;
        hn[(size_t)(C + 4 * cb + 0) * HW + pix] = cur[(size_t)(4 * cb + 0) * HW + pix];
        hn[(size_t)(C + 4 * cb + 1) * HW + pix] = cur[(size_t)(4 * cb + 1) * HW + pix];
        hn[(size_t)(C + 4 * cb + 2) * HW + pix] = cur[(size_t)(4 * cb + 2) * HW + pix];
        hn[(size_t)(C + 4 * cb + 3) * HW + pix] = cur[(size_t)(4 * cb + 3) * HW + pix];
    }
    hn[(size_t)128 * HW + pix] = fx;
    hn[(size_t)129 * HW + pix] = fy;
}

// ---------------------------------------------------------------------------
// Direct 3x3 conv (FFMA2, at packed-fp32 roofline) — conv1..3.
// ---------------------------------------------------------------------------
template<bool RELU>
__global__ __launch_bounds__(128) void conv3x3_k(
    const float* __restrict__ in, const float* __restrict__ wt,
    const float* __restrict__ bias, float* __restrict__ out,
    int Cin, int Cout)
{
    __shared__ float s_in[16][18][34];
    __shared__ float s_w[16][9][16];

    const int tx = threadIdx.x;
    const int ty = threadIdx.y;
    const int tid = ty * 32 + tx;
    const int x0 = blockIdx.x * 32;
    const int y0 = (blockIdx.y % 6) * 16;
    const int n  = blockIdx.y / 6;
    const int co0 = blockIdx.z * 16;
    const float* inN = in + (size_t)n * Cin * HW;

    unsigned long long acc[4][8];
    #pragma unroll
    for (int r = 0; r < 4; r++)
        #pragma unroll
        for (int o = 0; o < 8; o++) acc[r][o] = 0ull;

    for (int c0 = 0; c0 < Cin; c0 += 16) {
        for (int i = tid; i < 16 * 18 * 34; i += 128) {
            int ci  = i / (18 * 34);
            int rem = i % (18 * 34);
            int iy = rem / 34, ix = rem % 34;
            int gy = y0 + iy - 1, gx = x0 + ix - 1;
            int c = c0 + ci;
            float v = 0.f;
            if (c < Cin && (unsigned)gy < (unsigned)H && (unsigned)gx < (unsigned)W)
                v = inN[(size_t)c * HW + gy * W + gx];
            s_in[ci][iy][ix] = v;
        }
        for (int i = tid; i < 16 * 16 * 9; i += 128) {
            int co = i / 144, rem = i % 144;
            int ci = rem / 9, k = rem % 9;
            int c = c0 + ci;
            s_w[ci][k][co] = (c < Cin) ? wt[((size_t)(co0 + co) * Cin + c) * 9 + k] : 0.f;
        }
        __syncthreads();

        for (int ci = 0; ci < 16; ci++) {
            #pragma unroll
            for (int k = 0; k < 9; k++) {
                const int ky = k / 3, kx = k % 3;
                unsigned long long vv[4];
                #pragma unroll
                for (int r = 0; r < 4; r++) {
                    float v = s_in[ci][ty + 4 * r + ky][tx + kx];
                    vv[r] = pack2(v, v);
                }
                #pragma unroll
                for (int o = 0; o < 8; o++) {
                    unsigned long long wp =
                        *(const unsigned long long*)&s_w[ci][k][2 * o];
                    #pragma unroll
                    for (int r = 0; r < 4; r++)
                        ffma2(acc[r][o], vv[r], wp);
                }
            }
        }
        __syncthreads();
    }

    #pragma unroll
    for (int o = 0; o < 8; o++) {
        float b0 = bias[co0 + 2 * o];
        float b1 = bias[co0 + 2 * o + 1];
        #pragma unroll
        for (int r = 0; r < 4; r++) {
            float2 a = unpack2(acc[r][o]);
            a.x += b0; a.y += b1;
            if (RELU) {
                a.x = (a.x >= 0.f) ? a.x : NEG * a.x;
                a.y = (a.y >= 0.f) ? a.y : NEG * a.y;
            }
            size_t base = (size_t)(y0 + ty + 4 * r) * W + (x0 + tx);
            out[((size_t)n * Cout + co0 + 2 * o)     * HW + base] = a.x;
            out[((size_t)n * Cout + co0 + 2 * o + 1) * HW + base] = a.y;
        }
    }
}

// ---------------------------------------------------------------------------
// h1 (NCHW fp32) -> padded NHWC bf16 hi/lo pair (pad=1, 98x98)
// ---------------------------------------------------------------------------
__global__ void padbf16_k(const float* __restrict__ h1,
                          __nv_bfloat16* __restrict__ bhi,
                          __nv_bfloat16* __restrict__ blo) {
    int p = blockIdx.x * blockDim.x + threadIdx.x;
    if (p >= NB * PPIX2) return;
    int n = p / PPIX2, pp = p % PPIX2;
    int yy = pp / PW2 - 1, xx = pp % PW2 - 1;
    __nv_bfloat16* dh = bhi + (size_t)p * C;
    __nv_bfloat16* dl = blo + (size_t)p * C;
    if ((unsigned)yy < (unsigned)H && (unsigned)xx < (unsigned)W) {
        const float* hn = h1 + (size_t)n * C * HW + yy * W + xx;
        #pragma unroll 8
        for (int c = 0; c < C; c++) {
            float v = hn[(size_t)c * HW];
            __nv_bfloat16 hi = __float2bfloat16(v);
            __nv_bfloat16 lo = __float2bfloat16(v - __bfloat162float(hi));
            dh[c] = hi; dl[c] = lo;
        }
    } else {
        #pragma unroll 8
        for (int c = 0; c < C; c++) { dh[c] = __float2bfloat16(0.f); dl[c] = __float2bfloat16(0.f); }
    }
}

// ---------------------------------------------------------------------------
// w4 [432co][64ci][9] fp32 -> B-fragment layout for mma.sync:
// g_wf[((s*4+kc)*2+split)*54 + nt][lane] = u64{ b32{k0,k1}, b32{k8,k9} }
// where co = nt*8 + lane>>2, k = kc*16 + (lane&3)*2 (+8).
// ---------------------------------------------------------------------------
__global__ void wprep_k(const float* __restrict__ w4,
                        unsigned long long* __restrict__ wf) {
    int i = blockIdx.x * blockDim.x + threadIdx.x;
    if (i >= WF_ELEMS) return;
    int lane = i & 31;
    int t = i >> 5;
    int nt = t % 54; t /= 54;
    int split = t % 2; t /= 2;
    int kc = t % 4, s = t / 4;
    int co = nt * 8 + (lane >> 2);
    int kb = kc * 16 + (lane & 3) * 2;

    uint16_t e[4];
    #pragma unroll
    for (int j = 0; j < 4; j++) {
        int k = kb + (j >> 1) * 8 + (j & 1);
        float v = w4[((size_t)co * C + k) * 9 + s];
        __nv_bfloat16 hb = __float2bfloat16(v);
        __nv_bfloat16 r = split ? __float2bfloat16(v - __bfloat162float(hb)) : hb;
        e[j] = *(uint16_t*)&r;
    }
    uint32_t lo32 = (uint32_t)e[0] | ((uint32_t)e[1] << 16);
    uint32_t hi32 = (uint32_t)e[2] | ((uint32_t)e[3] << 16);
    wf[i] = (unsigned long long)lo32 | ((unsigned long long)hi32 << 32);
}

// ---------------------------------------------------------------------------
// conv4 via mma.sync bf16 (hi/lo split, 3 combos).
// Block = 1 image row (96 px = M) x 144 co (N), 4 warps (2x2),
// warp tile 48px x 72co = 3 mtiles x 9 ntiles.
// A: padded NHWC bf16 rows y..y+2 staged in SW128-swizzled smem; each shift
// is just a +-128B offset. B: prepacked frags, one LDG.64 per (nt, split).
// ---------------------------------------------------------------------------
__global__ __launch_bounds__(128) void conv4mma_k(
    const __nv_bfloat16* __restrict__ bhi,
    const __nv_bfloat16* __restrict__ blo,
    const unsigned long long* __restrict__ wf,
    const float* __restrict__ b4,
    float* __restrict__ o4)
{
    extern __shared__ uint8_t c4sm[];
    const int tid  = threadIdx.x;
    const int lane = tid & 31;
    const int wid  = tid >> 5;
    const int wm   = wid & 1;      // px half: 0..1 (48 px each)
    const int wn   = wid >> 1;     // co half: 0..1 (72 co each)
    const int y    = blockIdx.x;   // image row
    const int cc   = blockIdx.y;   // co chunk (144 each)
    const int n    = blockIdx.z;

    // Stage A: rows y..y+2 (contiguous in gmem), hi and lo, SW128-swizzled.
    {
        const uint4* srch = (const uint4*)(bhi + ((size_t)n * PPIX2 + (size_t)y * PW2) * C);
        const uint4* srcl = (const uint4*)(blo + ((size_t)n * PPIX2 + (size_t)y * PW2) * C);
        for (int i = tid; i < 3 * 98 * 8; i += 128) {
            uint32_t sw = SWZ128((uint32_t)(i * 16));
            *(uint4*)(c4sm + sw)            = srch[i];
            *(uint4*)(c4sm + C4_AREG + sw)  = srcl[i];
        }
    }
    __syncthreads();

    const uint32_t smA = smem_u32(c4sm);
    const int xoff = lane & 15;          // ldmatrix row within mtile
    const int c8b  = (lane >> 4) * 16;   // ldmatrix col-half byte offset

    float acc[3][9][4];
    #pragma unroll
    for (int mt = 0; mt < 3; mt++)
        #pragma unroll
        for (int nt = 0; nt < 9; nt++)
            #pragma unroll
            for (int j = 0; j < 4; j++) acc[mt][nt][j] = 0.f;

    for (int s = 0; s < 9; s++) {
        const int ky = s / 3, kx = s % 3;
        for (int kc = 0; kc < 4; kc++) {
            // A fragments (hi & lo) for 3 mtiles
            uint32_t ah[3][4], al[3][4];
            #pragma unroll
            for (int mt = 0; mt < 3; mt++) {
                uint32_t lin = (uint32_t)((ky * 98 + wm * 48 + mt * 16 + xoff + kx) * 128
                                          + kc * 32 + c8b);
                uint32_t ad = smA + SWZ128(lin);
                LDMATRIX_X4(ah[mt][0], ah[mt][1], ah[mt][2], ah[mt][3], ad);
                LDMATRIX_X4(al[mt][0], al[mt][1], al[mt][2], al[mt][3], ad + C4_AREG);
            }
            // B fragments for 9 ntiles (hi & lo) — prefetch all, then MMA
            unsigned long long bh[9], bl[9];
            const int ntg0 = cc * 18 + wn * 9;
            const size_t wbase = ((size_t)(s * 4 + kc) * 2) * 54 * 32 + lane;
            #pragma unroll
            for (int nt = 0; nt < 9; nt++) {
                bh[nt] = wf[wbase + (size_t)(ntg0 + nt) * 32];
                bl[nt] = wf[wbase + 54 * 32 + (size_t)(ntg0 + nt) * 32];
            }
            #pragma unroll
            for (int nt = 0; nt < 9; nt++) {
                uint32_t bh0 = (uint32_t)bh[nt], bh1 = (uint32_t)(bh[nt] >> 32);
                uint32_t bl0 = (uint32_t)bl[nt], bl1 = (uint32_t)(bl[nt] >> 32);
                #pragma unroll
                for (int mt = 0; mt < 3; mt++) {
                    MMA_BF16(acc[mt][nt], ah[mt], bh0, bh1);
                    MMA_BF16(acc[mt][nt], ah[mt], bl0, bl1);
                    MMA_BF16(acc[mt][nt], al[mt], bh0, bh1);
                }
            }
        }
    }

    // Epilogue: D frag (row=lane>>2 [+8], col=(lane&3)*2 [+1]) -> o4 + bias
    float* o4n = o4 + (size_t)n * COUT4 * HW;
    const int row0 = lane >> 2, col0 = (lane & 3) * 2;
    #pragma unroll
    for (int mt = 0; mt < 3; mt++) {
        int x0 = wm * 48 + mt * 16 + row0;
        size_t p0 = (size_t)y * W + x0;
        #pragma unroll
        for (int nt = 0; nt < 9; nt++) {
            int co = cc * 144 + wn * 72 + nt * 8 + col0;
            float b0 = b4[co], b1 = b4[co + 1];
            o4n[(size_t)co * HW + p0]           = acc[mt][nt][0] + b0;
            o4n[(size_t)(co + 1) * HW + p0]     = acc[mt][nt][1] + b1;
            o4n[(size_t)co * HW + p0 + 8]       = acc[mt][nt][2] + b0;
            o4n[(size_t)(co + 1) * HW + p0 + 8] = acc[mt][nt][3] + b1;
        }
    }
}

// ---------------------------------------------------------------------------
// Deform stage A: offsets + bilinear sampling from padded image.
// ---------------------------------------------------------------------------
__global__ __launch_bounds__(128) void sample_k(
    const float4* __restrict__ xp4, const float* __restrict__ fb,
    const float* __restrict__ ff, const float* __restrict__ o4,
    float4* __restrict__ samp)
{
    const int pix = blockIdx.x * 128 + threadIdx.x;
    const int dg  = blockIdx.y;
    const int n   = blockIdx.z;
    const int y   = pix / W;
    const int xx  = pix % W;

    int src_t;
    const float* flow;
    if (n < 6) { src_t = n + 1; flow = fb + (size_t)n * 2 * HW; }
    else       { src_t = n - 6; flow = ff + (size_t)(n - 6) * 2 * HW; }
    const float4* srcp = xp4 + (size_t)src_t * PPIX * (C / 4) + dg;
    const float* o4n   = o4 + (size_t)n * COUT4 * HW + pix;
    float4*      sampn = samp + ((size_t)n * 144 + (size_t)dg * 9) * HW + pix;

    const float fx = flow[pix];
    const float fy = flow[HW + pix];

    #pragma unroll
    for (int kk = 0; kk < 9; kk++) {
        float t0 = o4n[(size_t)(dg * 18 + kk * 2)     * HW];
        float t1 = o4n[(size_t)(dg * 18 + kk * 2 + 1) * HW];
        float tm = o4n[(size_t)(288 + dg * 9 + kk)    * HW];
        float m  = fast_sigmoid(tm);
        float py = 10.f * fast_tanh(t0) + fy + (float)(y  - 1 + kk / 3);
        float px = 10.f * fast_tanh(t1) + fx + (float)(xx - 1 + kk % 3);
        py = fminf(fmaxf(py, -2.f), (float)(H + 1));
        px = fminf(fmaxf(px, -2.f), (float)(W + 1));

        int iy0 = __float2int_rd(py), ix0 = __float2int_rd(px);
        float wy = py - (float)iy0, wx = px - (float)ix0;
        float wy1m = m * wy;
        float wy0m = m - wy1m;
        float wx0 = 1.f - wx;
        float w00 = wy0m * wx0, w01 = wy0m * wx;
        float w10 = wy1m * wx0, w11 = wy1m * wx;

        int base = (iy0 + 2) * PW + (ix0 + 2);
        ulonglong2 a = *(const ulonglong2*)(srcp + (size_t)base * (C / 4));
        ulonglong2 b = *(const ulonglong2*)(srcp + (size_t)(base + 1) * (C / 4));
        ulonglong2 c = *(const ulonglong2*)(srcp + (size_t)(base + PW) * (C / 4));
        ulonglong2 d = *(const ulonglong2*)(srcp + (size_t)(base + PW + 1) * (C / 4));

        unsigned long long w00p = pack2(w00, w00), w01p = pack2(w01, w01);
        unsigned long long w10p = pack2(w10, w10), w11p = pack2(w11, w11);
        unsigned long long v0 = 0ull, v1 = 0ull;
        ffma2(v0, w00p, a.x); ffma2(v1, w00p, a.y);
        ffma2(v0, w01p, b.x); ffma2(v1, w01p, b.y);
        ffma2(v0, w10p, c.x); ffma2(v1, w10p, c.y);
        ffma2(v0, w11p, d.x); ffma2(v1, w11p, d.y);

        ulonglong2 outv; outv.x = v0; outv.y = v1;
        *(ulonglong2*)&sampn[(size_t)kk * HW] = outv;
    }
}

// ---------------------------------------------------------------------------
// Deform stage B: 64x576 GEMM (permuted K), FFMA2.
// ---------------------------------------------------------------------------
#define GEMM_SS_FL   (64 * 132)
#define GEMM_SMEM_BYTES  (GEMM_SS_FL * 4 + 64 * 66 * 8)

__global__ __launch_bounds__(128) void gemm_k(
    const float4* __restrict__ samp, const float* __restrict__ dw,
    const float* __restrict__ db, float* __restrict__ out)
{
    extern __shared__ float sm[];
    float*  s_s  = sm;
    float2* s_w2 = (float2*)(sm + GEMM_SS_FL);

    const int tid = threadIdx.x;
    const int pxb = blockIdx.x * 128;
    const int n   = blockIdx.y;
    const float4* sampn = samp + (size_t)n * 144 * HW;

    const int pg = tid & 15;
    const int og = tid >> 4;

    unsigned long long acc[8][4];
    #pragma unroll
    for (int o = 0; o < 8; o++)
        #pragma unroll
        for (int p = 0; p < 4; p++) acc[o][p] = 0ull;

    for (int k0 = 0; k0 < 576; k0 += 64) {
        const int tap0 = k0 >> 2;
        #pragma unroll
        for (int l = 0; l < 16; l++) {
            float4 v = sampn[(size_t)(tap0 + l) * HW + pxb + tid];
            s_s[(l * 4 + 0) * 132 + tid] = v.x;
            s_s[(l * 4 + 1) * 132 + tid] = v.y;
            s_s[(l * 4 + 2) * 132 + tid] = v.z;
            s_s[(l * 4 + 3) * 132 + tid] = v.w;
        }
        for (int i = tid; i < 64 * 64; i += 128) {
            int co = i >> 6, jj = i & 63;
            int j = k0 + jj;
            int t = j >> 2, cg = j & 3;
            int dg = t / 9, kkid = t - 9 * dg;
            int k = (dg * 4 + cg) * 9 + kkid;
            float w = dw[(size_t)co * 576 + k];
            s_w2[jj * 66 + co] = make_float2(w, w);
        }
        __syncthreads();

        #pragma unroll 2
        for (int kk = 0; kk < 64; kk++) {
            ulonglong2 p0 = *(const ulonglong2*)&s_s[kk * 132 + pg * 8];
            ulonglong2 p1 = *(const ulonglong2*)&s_s[kk * 132 + pg * 8 + 4];
            unsigned long long wq[8];
            #pragma unroll
            for (int j = 0; j < 4; j++) {
                ulonglong2 wv = *(const ulonglong2*)&s_w2[kk * 66 + og * 8 + 2 * j];
                wq[2 * j]     = wv.x;
                wq[2 * j + 1] = wv.y;
            }
            #pragma unroll
            for (int o = 0; o < 8; o++) {
                ffma2(acc[o][0], wq[o], p0.x);
                ffma2(acc[o][1], wq[o], p0.y);
                ffma2(acc[o][2], wq[o], p1.x);
                ffma2(acc[o][3], wq[o], p1.y);
            }
        }
        __syncthreads();
    }

    float* outn = (n < 6) ? out + (size_t)n * C * HW
                          : out + (size_t)(7 + (n - 6) + 1) * C * HW;
    #pragma unroll
    for (int o = 0; o < 8; o++) {
        int co = og * 8 + o;
        float bv = db[co];
        float2 a0 = unpack2(acc[o][0]);
        float2 a1 = unpack2(acc[o][1]);
        float2 a2 = unpack2(acc[o][2]);
        float2 a3 = unpack2(acc[o][3]);
        float4 v0 = make_float4(a0.x + bv, a0.y + bv, a1.x + bv, a1.y + bv);
        float4 v1 = make_float4(a2.x + bv, a2.y + bv, a3.x + bv, a3.y + bv);
        size_t base = (size_t)co * HW + pxb + pg * 8;
        *(float4*)&outn[base]     = v0;
        *(float4*)&outn[base + 4] = v1;
    }
}

// ---------------------------------------------------------------------------
// Launch
// ---------------------------------------------------------------------------
extern "C" void kernel_launch(void* const* d_in, const int* in_sizes, int n_in,
                              void* d_out, int out_size)
{
    const float* x  = (const float*)d_in[0];
    const float* fb = (const float*)d_in[1];
    const float* ff = (const float*)d_in[2];
    const float* w1 = (const float*)d_in[3];  const float* b1 = (const float*)d_in[4];
    const float* w2 = (const float*)d_in[5];  const float* b2 = (const float*)d_in[6];
    const float* w3 = (const float*)d_in[7];  const float* b3 = (const float*)d_in[8];
    const float* w4 = (const float*)d_in[9];  const float* b4 = (const float*)d_in[10];
    const float* dw = (const float*)d_in[11]; const float* db = (const float*)d_in[12];
    float* out = (float*)d_out;

    float *h0, *h1, *h2, *o4, *sp, *xp;
    __nv_bfloat16 *bhi, *blo;
    unsigned long long *wfp;
    cudaGetSymbolAddress((void**)&h0, g_h0);
    cudaGetSymbolAddress((void**)&h1, g_h1);
    cudaGetSymbolAddress((void**)&h2, g_h2);
    cudaGetSymbolAddress((void**)&o4, g_o4);
    cudaGetSymbolAddress((void**)&sp, g_samp);
    cudaGetSymbolAddress((void**)&xp, g_xp);
    cudaGetSymbolAddress((void**)&bhi, g_bhi);
    cudaGetSymbolAddress((void**)&blo, g_blo);
    cudaGetSymbolAddress((void**)&wfp, g_wf);

    {
        int n4 = 2 * C * HW / 4;
        zero_k<<<(n4 + 255) / 256, 256>>>((float4*)(out + (size_t)6 * C * HW), n4);
    }
    pad_k<<<(T * PPIX + 127) / 128, 128>>>(x, (float4*)xp);
    wprep_k<<<(WF_ELEMS + 255) / 256, 256>>>(w4, wfp);
    warp_concat_k<<<(NB * HW + 255) / 256, 256>>>(x, (const float4*)xp, fb, ff, h0);

    dim3 cb(32, 4);
    conv3x3_k<true><<<dim3(3, 72, 4), cb>>>(h0, w1, b1, h1, CIN1, C);
    conv3x3_k<true><<<dim3(3, 72, 4), cb>>>(h1, w2, b2, h2, C,    C);
    conv3x3_k<true><<<dim3(3, 72, 4), cb>>>(h2, w3, b3, h1, C,    C);

    padbf16_k<<<(NB * PPIX2 + 127) / 128, 128>>>(h1, bhi, blo);

    cudaFuncSetAttribute(conv4mma_k, cudaFuncAttributeMaxDynamicSharedMemorySize,
                         C4_SMEM);
    conv4mma_k<<<dim3(96, 3, NB), 128, C4_SMEM>>>(bhi, blo, wfp, b4, o4);

    sample_k<<<dim3(72, 16, NB), 128>>>((const float4*)xp, fb, ff, o4, (float4*)sp);

    cudaFuncSetAttribute(gemm_k, cudaFuncAttributeMaxDynamicSharedMemorySize,
                         GEMM_SMEM_BYTES);
    gemm_k<<<dim3(72, NB), 128, GEMM_SMEM_BYTES>>>((const float4*)sp, dw, db, out);
}

// round 11
// speedup vs baseline: 2.2634x; 1.0057x over previous
#include <cuda_runtime.h>
#include <cuda_bf16.h>
#include <math.h>
#include <cstdint>

// Problem constants
#define H     96
#define W     96
#define HW    9216           // H*W
#define C     64
#define T     7
#define NB    12             // 6 backward + 6 forward frame pairs
#define CIN1  130            // warped(64) + x_cur(64) + flow(2)
#define COUT4 432            // 3 * 9 * 16
#define NEG   0.1f
#define PW    101            // padded width/height for x (pad=2 + slack)
#define PPIX  (PW * PW)
#define PW2   98             // padded width for h1 (pad=1)
#define PPIX2 (PW2 * PW2)    // 9604

// ---------------------------------------------------------------------------
// Packed fp32x2 helpers
// ---------------------------------------------------------------------------
__device__ __forceinline__ void ffma2(unsigned long long& d,
                                      unsigned long long a,
                                      unsigned long long b) {
    asm("fma.rn.f32x2 %0, %1, %2, %0;" : "+l"(d) : "l"(a), "l"(b));
}
__device__ __forceinline__ unsigned long long pack2(float lo, float hi) {
    unsigned long long r;
    asm("mov.b64 %0, {%1, %2};" : "=l"(r) : "f"(lo), "f"(hi));
    return r;
}
__device__ __forceinline__ float2 unpack2(unsigned long long v) {
    float2 r;
    asm("mov.b64 {%0, %1}, %2;" : "=f"(r.x), "=f"(r.y) : "l"(v));
    return r;
}
__device__ __forceinline__ float fast_rcp(float x) {
    float r;
    asm("rcp.approx.f32 %0, %1;" : "=f"(r) : "f"(x));
    return r;
}
__device__ __forceinline__ float fast_tanh(float x) {
    float e = __expf(2.f * x);
    return fmaf(-2.f, fast_rcp(e + 1.f), 1.f);
}
__device__ __forceinline__ float fast_sigmoid(float x) {
    return fast_rcp(1.f + __expf(-x));
}

// ---------------------------------------------------------------------------
// mma.sync / ldmatrix helpers (legacy tensor-core path, compute_100-safe)
// ---------------------------------------------------------------------------
__device__ __forceinline__ uint32_t smem_u32(const void* p) {
    uint32_t a;
    asm("{ .reg .u64 t; cvta.to.shared.u64 t, %1; cvt.u32.u64 %0, t; }"
        : "=r"(a) : "l"(p));
    return a;
}
#define LDMATRIX_X4(r0, r1, r2, r3, addr) \
    asm volatile("ldmatrix.sync.aligned.m8n8.x4.shared.b16 {%0,%1,%2,%3}, [%4];" \
                 : "=r"(r0), "=r"(r1), "=r"(r2), "=r"(r3) : "r"(addr))
#define MMA_BF16(d, a, b0, b1) \
    asm volatile("mma.sync.aligned.m16n8k16.row.col.f32.bf16.bf16.f32 " \
                 "{%0,%1,%2,%3}, {%4,%5,%6,%7}, {%8,%9}, {%0,%1,%2,%3};" \
                 : "+f"((d)[0]), "+f"((d)[1]), "+f"((d)[2]), "+f"((d)[3]) \
                 : "r"((a)[0]), "r"((a)[1]), "r"((a)[2]), "r"((a)[3]), \
                   "r"(b0), "r"(b1))
#define SWZ128(off) ((off) ^ (((off) >> 3) & 0x70))

// A-stage region: 3 padded rows x 98 px x 64 ci bf16 = 37632 B, round to 37888
#define C4_AREG   37888
#define C4_SMEM   (2 * C4_AREG)     // hi + lo stages (75776 B)
#define WF_ELEMS  (9 * 4 * 2 * 54 * 32)   // per-(shift,kchunk,split,ntile,lane) u64

// ---------------------------------------------------------------------------
// Scratch buffers
// ---------------------------------------------------------------------------
__device__ float g_h0[NB * CIN1 * HW];
__device__ float g_h1[NB * C * HW];
__device__ float g_h2[NB * C * HW];
__device__ float g_o4[NB * COUT4 * HW];
__device__ float g_samp[NB * 144 * HW * 4];
__device__ float g_xp[T * PPIX * C];
__device__ __nv_bfloat16 g_bhi[NB * PPIX2 * C];       // h1 padded NHWC bf16 hi
__device__ __nv_bfloat16 g_blo[NB * PPIX2 * C];       // h1 padded NHWC bf16 lo
__device__ unsigned long long g_wf[WF_ELEMS];         // prepacked W4 B-frags

// ---------------------------------------------------------------------------
__global__ void zero_k(float4* __restrict__ p, int n4) {
    int i = blockIdx.x * blockDim.x + threadIdx.x;
    if (i < n4) p[i] = make_float4(0.f, 0.f, 0.f, 0.f);
}

// x -> zero-padded NHWC (pad=2)
__global__ void pad_k(const float* __restrict__ x, float4* __restrict__ xp4) {
    int p = blockIdx.x * blockDim.x + threadIdx.x;
    if (p >= T * PPIX) return;
    int t = p / PPIX, rem = p % PPIX;
    int yy = rem / PW - 2, xx = rem % PW - 2;
    float4* dst = xp4 + (size_t)p * (C / 4);
    if ((unsigned)yy < (unsigned)H && (unsigned)xx < (unsigned)W) {
        const float* xn = x + (size_t)t * C * HW + yy * W + xx;
        #pragma unroll
        for (int cb = 0; cb < C / 4; cb++) {
            float4 v;
            v.x = xn[(size_t)(4 * cb + 0) * HW];
            v.y = xn[(size_t)(4 * cb + 1) * HW];
            v.z = xn[(size_t)(4 * cb + 2) * HW];
            v.w = xn[(size_t)(4 * cb + 3) * HW];
            dst[cb] = v;
        }
    } else {
        float4 z = make_float4(0.f, 0.f, 0.f, 0.f);
        #pragma unroll
        for (int cb = 0; cb < C / 4; cb++) dst[cb] = z;
    }
}

// ---------------------------------------------------------------------------
// Stage 1: flow-warp + concat
// ---------------------------------------------------------------------------
__global__ void warp_concat_k(const float* __restrict__ x,
                              const float4* __restrict__ xp4,
                              const float* __restrict__ fb,
                              const float* __restrict__ ff,
                              float* __restrict__ h0) {
    int p = blockIdx.x * blockDim.x + threadIdx.x;
    if (p >= NB * HW) return;
    int n = p / HW, pix = p % HW;
    int yy = pix / W, xx = pix % W;

    int src_t, cur_t;
    const float* flow;
    if (n < 6) { src_t = n + 1; cur_t = n;     flow = fb + (size_t)n * 2 * HW; }
    else       { int m = n - 6; src_t = m; cur_t = m + 1; flow = ff + (size_t)m * 2 * HW; }

    float fx = flow[pix];
    float fy = flow[HW + pix];
    float px = fminf(fmaxf((float)xx + fx, -2.f), (float)(W + 1));
    float py = fminf(fmaxf((float)yy + fy, -2.f), (float)(H + 1));

    int iy0 = __float2int_rd(py), ix0 = __float2int_rd(px);
    float wy = py - (float)iy0, wx = px - (float)ix0;
    float w00 = (1.f - wy) * (1.f - wx);
    float w01 = (1.f - wy) * wx;
    float w10 = wy * (1.f - wx);
    float w11 = wy * wx;

    int base = (iy0 + 2) * PW + (ix0 + 2);
    const float4* sp = xp4 + (size_t)src_t * PPIX * (C / 4);
    const float4* s00 = sp + (size_t)base * (C / 4);
    const float4* s01 = sp + (size_t)(base + 1) * (C / 4);
    const float4* s10 = sp + (size_t)(base + PW) * (C / 4);
    const float4* s11 = sp + (size_t)(base + PW + 1) * (C / 4);
    const float* cur = x + (size_t)cur_t * C * HW;
    float* hn = h0 + (size_t)n * CIN1 * HW;

    #pragma unroll 4
    for (int cb = 0; cb < C / 4; cb++) {
        float4 a = s00[cb], b = s01[cb], c = s10[cb], d = s11[cb];
        float4 v;
        v.x = w00 * a.x + w01 * b.x + w10 * c.x + w11 * d.x;
        v.y = w00 * a.y + w01 * b.y + w10 * c.y + w11 * d.y;
        v.z = w00 * a.z + w01 * b.z + w10 * c.z + w11 * d.z;
        v.w = w00 * a.w + w01 * b.w + w10 * c.w + w11 * d.w;
        hn[(size_t)(4 * cb + 0) * HW + pix] = v.x;
        hn[(size_t)(4 * cb + 1) * HW + pix] = v.y;
        hn[(size_t)(4 * cb + 2) * HW + pix] = v.z;
        hn[(size_t)(4 * cb + 3) * HW + pix] = v.w;
        hn[(size_t)(C + 4 * cb + 0) * HW + pix] = cur[(size_t)(4 * cb + 0) * HW + pix];
        hn[(size_t)(C + 4 * cb + 1) * HW + pix] = cur[(size_t)(4 * cb + 1) * HW + pix];
        hn[(size_t)(C + 4 * cb + 2) * HW + pix] = cur[(size_t)(4 * cb + 2) * HW + pix];
        hn[(size_t)(C + 4 * cb + 3) * HW + pix] = cur[(size_t)(4 * cb + 3) * HW + pix];
    }
    hn[(size_t)128 * HW + pix] = fx;
    hn[(size_t)129 * HW + pix] = fy;
}

// ---------------------------------------------------------------------------
// Direct 3x3 conv (FFMA2, at packed-fp32 roofline) — conv1..3.
// ---------------------------------------------------------------------------
template<bool RELU>
__global__ __launch_bounds__(128) void conv3x3_k(
    const float* __restrict__ in, const float* __restrict__ wt,
    const float* __restrict__ bias, float* __restrict__ out,
    int Cin, int Cout)
{
    __shared__ float s_in[16][18][34];
    __shared__ float s_w[16][9][16];

    const int tx = threadIdx.x;
    const int ty = threadIdx.y;
    const int tid = ty * 32 + tx;
    const int x0 = blockIdx.x * 32;
    const int y0 = (blockIdx.y % 6) * 16;
    const int n  = blockIdx.y / 6;
    const int co0 = blockIdx.z * 16;
    const float* inN = in + (size_t)n * Cin * HW;

    unsigned long long acc[4][8];
    #pragma unroll
    for (int r = 0; r < 4; r++)
        #pragma unroll
        for (int o = 0; o < 8; o++) acc[r][o] = 0ull;

    for (int c0 = 0; c0 < Cin; c0 += 16) {
        for (int i = tid; i < 16 * 18 * 34; i += 128) {
            int ci  = i / (18 * 34);
            int rem = i % (18 * 34);
            int iy = rem / 34, ix = rem % 34;
            int gy = y0 + iy - 1, gx = x0 + ix - 1;
            int c = c0 + ci;
            float v = 0.f;
            if (c < Cin && (unsigned)gy < (unsigned)H && (unsigned)gx < (unsigned)W)
                v = inN[(size_t)c * HW + gy * W + gx];
            s_in[ci][iy][ix] = v;
        }
        for (int i = tid; i < 16 * 16 * 9; i += 128) {
            int co = i / 144, rem = i % 144;
            int ci = rem / 9, k = rem % 9;
            int c = c0 + ci;
            s_w[ci][k][co] = (c < Cin) ? wt[((size_t)(co0 + co) * Cin + c) * 9 + k] : 0.f;
        }
        __syncthreads();

        for (int ci = 0; ci < 16; ci++) {
            #pragma unroll
            for (int k = 0; k < 9; k++) {
                const int ky = k / 3, kx = k % 3;
                unsigned long long vv[4];
                #pragma unroll
                for (int r = 0; r < 4; r++) {
                    float v = s_in[ci][ty + 4 * r + ky][tx + kx];
                    vv[r] = pack2(v, v);
                }
                #pragma unroll
                for (int o = 0; o < 8; o++) {
                    unsigned long long wp =
                        *(const unsigned long long*)&s_w[ci][k][2 * o];
                    #pragma unroll
                    for (int r = 0; r < 4; r++)
                        ffma2(acc[r][o], vv[r], wp);
                }
            }
        }
        __syncthreads();
    }

    #pragma unroll
    for (int o = 0; o < 8; o++) {
        float b0 = bias[co0 + 2 * o];
        float b1 = bias[co0 + 2 * o + 1];
        #pragma unroll
        for (int r = 0; r < 4; r++) {
            float2 a = unpack2(acc[r][o]);
            a.x += b0; a.y += b1;
            if (RELU) {
                a.x = (a.x >= 0.f) ? a.x : NEG * a.x;
                a.y = (a.y >= 0.f) ? a.y : NEG * a.y;
            }
            size_t base = (size_t)(y0 + ty + 4 * r) * W + (x0 + tx);
            out[((size_t)n * Cout + co0 + 2 * o)     * HW + base] = a.x;
            out[((size_t)n * Cout + co0 + 2 * o + 1) * HW + base] = a.y;
        }
    }
}

// ---------------------------------------------------------------------------
// h1 (NCHW fp32) -> padded NHWC bf16 hi/lo pair (pad=1, 98x98)
// ---------------------------------------------------------------------------
__global__ void padbf16_k(const float* __restrict__ h1,
                          __nv_bfloat16* __restrict__ bhi,
                          __nv_bfloat16* __restrict__ blo) {
    int p = blockIdx.x * blockDim.x + threadIdx.x;
    if (p >= NB * PPIX2) return;
    int n = p / PPIX2, pp = p % PPIX2;
    int yy = pp / PW2 - 1, xx = pp % PW2 - 1;
    __nv_bfloat16* dh = bhi + (size_t)p * C;
    __nv_bfloat16* dl = blo + (size_t)p * C;
    if ((unsigned)yy < (unsigned)H && (unsigned)xx < (unsigned)W) {
        const float* hn = h1 + (size_t)n * C * HW + yy * W + xx;
        #pragma unroll 8
        for (int c = 0; c < C; c++) {
            float v = hn[(size_t)c * HW];
            __nv_bfloat16 hi = __float2bfloat16(v);
            __nv_bfloat16 lo = __float2bfloat16(v - __bfloat162float(hi));
            dh[c] = hi; dl[c] = lo;
        }
    } else {
        #pragma unroll 8
        for (int c = 0; c < C; c++) { dh[c] = __float2bfloat16(0.f); dl[c] = __float2bfloat16(0.f); }
    }
}

// ---------------------------------------------------------------------------
// w4 [432co][64ci][9] fp32 -> B-fragment layout for mma.sync:
// g_wf[((s*4+kc)*2+split)*54 + nt][lane] = u64{ b32{k0,k1}, b32{k8,k9} }
// where co = nt*8 + lane>>2, k = kc*16 + (lane&3)*2 (+8).
// ---------------------------------------------------------------------------
__global__ void wprep_k(const float* __restrict__ w4,
                        unsigned long long* __restrict__ wf) {
    int i = blockIdx.x * blockDim.x + threadIdx.x;
    if (i >= WF_ELEMS) return;
    int lane = i & 31;
    int t = i >> 5;
    int nt = t % 54; t /= 54;
    int split = t % 2; t /= 2;
    int kc = t % 4, s = t / 4;
    int co = nt * 8 + (lane >> 2);
    int kb = kc * 16 + (lane & 3) * 2;

    uint16_t e[4];
    #pragma unroll
    for (int j = 0; j < 4; j++) {
        int k = kb + (j >> 1) * 8 + (j & 1);
        float v = w4[((size_t)co * C + k) * 9 + s];
        __nv_bfloat16 hb = __float2bfloat16(v);
        __nv_bfloat16 r = split ? __float2bfloat16(v - __bfloat162float(hb)) : hb;
        e[j] = *(uint16_t*)&r;
    }
    uint32_t lo32 = (uint32_t)e[0] | ((uint32_t)e[1] << 16);
    uint32_t hi32 = (uint32_t)e[2] | ((uint32_t)e[3] << 16);
    wf[i] = (unsigned long long)lo32 | ((unsigned long long)hi32 << 32);
}

// ---------------------------------------------------------------------------
// conv4 via mma.sync bf16 (hi/lo split, 3 combos).
// Block = 1 image row (96 px = M) x 144 co (N), 4 warps (2x2),
// warp tile 48px x 72co = 3 mtiles x 9 ntiles.
// A: padded NHWC bf16 rows y..y+2 staged in SW128-swizzled smem; each shift
// is just a +-128B offset. B: prepacked frags, one LDG.64 per (nt, split).
// ---------------------------------------------------------------------------
__global__ __launch_bounds__(128) void conv4mma_k(
    const __nv_bfloat16* __restrict__ bhi,
    const __nv_bfloat16* __restrict__ blo,
    const unsigned long long* __restrict__ wf,
    const float* __restrict__ b4,
    float* __restrict__ o4)
{
    extern __shared__ uint8_t c4sm[];
    const int tid  = threadIdx.x;
    const int lane = tid & 31;
    const int wid  = tid >> 5;
    const int wm   = wid & 1;      // px half: 0..1 (48 px each)
    const int wn   = wid >> 1;     // co half: 0..1 (72 co each)
    const int y    = blockIdx.x;   // image row
    const int cc   = blockIdx.y;   // co chunk (144 each)
    const int n    = blockIdx.z;

    // Stage A: rows y..y+2 (contiguous in gmem), hi and lo, SW128-swizzled.
    {
        const uint4* srch = (const uint4*)(bhi + ((size_t)n * PPIX2 + (size_t)y * PW2) * C);
        const uint4* srcl = (const uint4*)(blo + ((size_t)n * PPIX2 + (size_t)y * PW2) * C);
        for (int i = tid; i < 3 * 98 * 8; i += 128) {
            uint32_t sw = SWZ128((uint32_t)(i * 16));
            *(uint4*)(c4sm + sw)            = srch[i];
            *(uint4*)(c4sm + C4_AREG + sw)  = srcl[i];
        }
    }
    __syncthreads();

    const uint32_t smA = smem_u32(c4sm);
    const int xoff = lane & 15;          // ldmatrix row within mtile
    const int c8b  = (lane >> 4) * 16;   // ldmatrix col-half byte offset

    float acc[3][9][4];
    #pragma unroll
    for (int mt = 0; mt < 3; mt++)
        #pragma unroll
        for (int nt = 0; nt < 9; nt++)
            #pragma unroll
            for (int j = 0; j < 4; j++) acc[mt][nt][j] = 0.f;

    for (int s = 0; s < 9; s++) {
        const int ky = s / 3, kx = s % 3;
        for (int kc = 0; kc < 4; kc++) {
            // A fragments (hi & lo) for 3 mtiles
            uint32_t ah[3][4], al[3][4];
            #pragma unroll
            for (int mt = 0; mt < 3; mt++) {
                uint32_t lin = (uint32_t)((ky * 98 + wm * 48 + mt * 16 + xoff + kx) * 128
                                          + kc * 32 + c8b);
                uint32_t ad = smA + SWZ128(lin);
                LDMATRIX_X4(ah[mt][0], ah[mt][1], ah[mt][2], ah[mt][3], ad);
                LDMATRIX_X4(al[mt][0], al[mt][1], al[mt][2], al[mt][3], ad + C4_AREG);
            }
            // B fragments for 9 ntiles (hi & lo) — prefetch all, then MMA
            unsigned long long bh[9], bl[9];
            const int ntg0 = cc * 18 + wn * 9;
            const size_t wbase = ((size_t)(s * 4 + kc) * 2) * 54 * 32 + lane;
            #pragma unroll
            for (int nt = 0; nt < 9; nt++) {
                bh[nt] = wf[wbase + (size_t)(ntg0 + nt) * 32];
                bl[nt] = wf[wbase + 54 * 32 + (size_t)(ntg0 + nt) * 32];
            }
            #pragma unroll
            for (int nt = 0; nt < 9; nt++) {
                uint32_t bh0 = (uint32_t)bh[nt], bh1 = (uint32_t)(bh[nt] >> 32);
                uint32_t bl0 = (uint32_t)bl[nt], bl1 = (uint32_t)(bl[nt] >> 32);
                #pragma unroll
                for (int mt = 0; mt < 3; mt++) {
                    MMA_BF16(acc[mt][nt], ah[mt], bh0, bh1);
                    MMA_BF16(acc[mt][nt], ah[mt], bl0, bl1);
                    MMA_BF16(acc[mt][nt], al[mt], bh0, bh1);
                }
            }
        }
    }

    // Epilogue: D frag (row=lane>>2 [+8], col=(lane&3)*2 [+1]) -> o4 + bias
    float* o4n = o4 + (size_t)n * COUT4 * HW;
    const int row0 = lane >> 2, col0 = (lane & 3) * 2;
    #pragma unroll
    for (int mt = 0; mt < 3; mt++) {
        int x0 = wm * 48 + mt * 16 + row0;
        size_t p0 = (size_t)y * W + x0;
        #pragma unroll
        for (int nt = 0; nt < 9; nt++) {
            int co = cc * 144 + wn * 72 + nt * 8 + col0;
            float b0 = b4[co], b1 = b4[co + 1];
            o4n[(size_t)co * HW + p0]           = acc[mt][nt][0] + b0;
            o4n[(size_t)(co + 1) * HW + p0]     = acc[mt][nt][1] + b1;
            o4n[(size_t)co * HW + p0 + 8]       = acc[mt][nt][2] + b0;
            o4n[(size_t)(co + 1) * HW + p0 + 8] = acc[mt][nt][3] + b1;
        }
    }
}

// ---------------------------------------------------------------------------
// Deform stage A: offsets + bilinear sampling from padded image.
// ---------------------------------------------------------------------------
__global__ __launch_bounds__(128) void sample_k(
    const float4* __restrict__ xp4, const float* __restrict__ fb,
    const float* __restrict__ ff, const float* __restrict__ o4,
    float4* __restrict__ samp)
{
    const int pix = blockIdx.x * 128 + threadIdx.x;
    const int dg  = blockIdx.y;
    const int n   = blockIdx.z;
    const int y   = pix / W;
    const int xx  = pix % W;

    int src_t;
    const float* flow;
    if (n < 6) { src_t = n + 1; flow = fb + (size_t)n * 2 * HW; }
    else       { src_t = n - 6; flow = ff + (size_t)(n - 6) * 2 * HW; }
    const float4* srcp = xp4 + (size_t)src_t * PPIX * (C / 4) + dg;
    const float* o4n   = o4 + (size_t)n * COUT4 * HW + pix;
    float4*      sampn = samp + ((size_t)n * 144 + (size_t)dg * 9) * HW + pix;

    const float fx = flow[pix];
    const float fy = flow[HW + pix];

    #pragma unroll
    for (int kk = 0; kk < 9; kk++) {
        float t0 = o4n[(size_t)(dg * 18 + kk * 2)     * HW];
        float t1 = o4n[(size_t)(dg * 18 + kk * 2 + 1) * HW];
        float tm = o4n[(size_t)(288 + dg * 9 + kk)    * HW];
        float m  = fast_sigmoid(tm);
        float py = 10.f * fast_tanh(t0) + fy + (float)(y  - 1 + kk / 3);
        float px = 10.f * fast_tanh(t1) + fx + (float)(xx - 1 + kk % 3);
        py = fminf(fmaxf(py, -2.f), (float)(H + 1));
        px = fminf(fmaxf(px, -2.f), (float)(W + 1));

        int iy0 = __float2int_rd(py), ix0 = __float2int_rd(px);
        float wy = py - (float)iy0, wx = px - (float)ix0;
        float wy1m = m * wy;
        float wy0m = m - wy1m;
        float wx0 = 1.f - wx;
        float w00 = wy0m * wx0, w01 = wy0m * wx;
        float w10 = wy1m * wx0, w11 = wy1m * wx;

        int base = (iy0 + 2) * PW + (ix0 + 2);
        ulonglong2 a = *(const ulonglong2*)(srcp + (size_t)base * (C / 4));
        ulonglong2 b = *(const ulonglong2*)(srcp + (size_t)(base + 1) * (C / 4));
        ulonglong2 c = *(const ulonglong2*)(srcp + (size_t)(base + PW) * (C / 4));
        ulonglong2 d = *(const ulonglong2*)(srcp + (size_t)(base + PW + 1) * (C / 4));

        unsigned long long w00p = pack2(w00, w00), w01p = pack2(w01, w01);
        unsigned long long w10p = pack2(w10, w10), w11p = pack2(w11, w11);
        unsigned long long v0 = 0ull, v1 = 0ull;
        ffma2(v0, w00p, a.x); ffma2(v1, w00p, a.y);
        ffma2(v0, w01p, b.x); ffma2(v1, w01p, b.y);
        ffma2(v0, w10p, c.x); ffma2(v1, w10p, c.y);
        ffma2(v0, w11p, d.x); ffma2(v1, w11p, d.y);

        ulonglong2 outv; outv.x = v0; outv.y = v1;
        *(ulonglong2*)&sampn[(size_t)kk * HW] = outv;
    }
}

// ---------------------------------------------------------------------------
// Deform stage B: 64x576 GEMM (permuted K), FFMA2.
// ---------------------------------------------------------------------------
#define GEMM_SS_FL   (64 * 132)
#define GEMM_SMEM_BYTES  (GEMM_SS_FL * 4 + 64 * 66 * 8)

__global__ __launch_bounds__(128) void gemm_k(
    const float4* __restrict__ samp, const float* __restrict__ dw,
    const float* __restrict__ db, float* __restrict__ out)
{
    extern __shared__ float sm[];
    float*  s_s  = sm;
    float2* s_w2 = (float2*)(sm + GEMM_SS_FL);

    const int tid = threadIdx.x;
    const int pxb = blockIdx.x * 128;
    const int n   = blockIdx.y;
    const float4* sampn = samp + (size_t)n * 144 * HW;

    const int pg = tid & 15;
    const int og = tid >> 4;

    unsigned long long acc[8][4];
    #pragma unroll
    for (int o = 0; o < 8; o++)
        #pragma unroll
        for (int p = 0; p < 4; p++) acc[o][p] = 0ull;

    for (int k0 = 0; k0 < 576; k0 += 64) {
        const int tap0 = k0 >> 2;
        #pragma unroll
        for (int l = 0; l < 16; l++) {
            float4 v = sampn[(size_t)(tap0 + l) * HW + pxb + tid];
            s_s[(l * 4 + 0) * 132 + tid] = v.x;
            s_s[(l * 4 + 1) * 132 + tid] = v.y;
            s_s[(l * 4 + 2) * 132 + tid] = v.z;
            s_s[(l * 4 + 3) * 132 + tid] = v.w;
        }
        for (int i = tid; i < 64 * 64; i += 128) {
            int co = i >> 6, jj = i & 63;
            int j = k0 + jj;
            int t = j >> 2, cg = j & 3;
            int dg = t / 9, kkid = t - 9 * dg;
            int k = (dg * 4 + cg) * 9 + kkid;
            float w = dw[(size_t)co * 576 + k];
            s_w2[jj * 66 + co] = make_float2(w, w);
        }
        __syncthreads();

        #pragma unroll 2
        for (int kk = 0; kk < 64; kk++) {
            ulonglong2 p0 = *(const ulonglong2*)&s_s[kk * 132 + pg * 8];
            ulonglong2 p1 = *(const ulonglong2*)&s_s[kk * 132 + pg * 8 + 4];
            unsigned long long wq[8];
            #pragma unroll
            for (int j = 0; j < 4; j++) {
                ulonglong2 wv = *(const ulonglong2*)&s_w2[kk * 66 + og * 8 + 2 * j];
                wq[2 * j]     = wv.x;
                wq[2 * j + 1] = wv.y;
            }
            #pragma unroll
            for (int o = 0; o < 8; o++) {
                ffma2(acc[o][0], wq[o], p0.x);
                ffma2(acc[o][1], wq[o], p0.y);
                ffma2(acc[o][2], wq[o], p1.x);
                ffma2(acc[o][3], wq[o], p1.y);
            }
        }
        __syncthreads();
    }

    float* outn = (n < 6) ? out + (size_t)n * C * HW
                          : out + (size_t)(7 + (n - 6) + 1) * C * HW;
    #pragma unroll
    for (int o = 0; o < 8; o++) {
        int co = og * 8 + o;
        float bv = db[co];
        float2 a0 = unpack2(acc[o][0]);
        float2 a1 = unpack2(acc[o][1]);
        float2 a2 = unpack2(acc[o][2]);
        float2 a3 = unpack2(acc[o][3]);
        float4 v0 = make_float4(a0.x + bv, a0.y + bv, a1.x + bv, a1.y + bv);
        float4 v1 = make_float4(a2.x + bv, a2.y + bv, a3.x + bv, a3.y + bv);
        size_t base = (size_t)co * HW + pxb + pg * 8;
        *(float4*)&outn[base]     = v0;
        *(float4*)&outn[base + 4] = v1;
    }
}

// ---------------------------------------------------------------------------
// Launch
// ---------------------------------------------------------------------------
extern "C" void kernel_launch(void* const* d_in, const int* in_sizes, int n_in,
                              void* d_out, int out_size)
{
    const float* x  = (const float*)d_in[0];
    const float* fb = (const float*)d_in[1];
    const float* ff = (const float*)d_in[2];
    const float* w1 = (const float*)d_in[3];  const float* b1 = (const float*)d_in[4];
    const float* w2 = (const float*)d_in[5];  const float* b2 = (const float*)d_in[6];
    const float* w3 = (const float*)d_in[7];  const float* b3 = (const float*)d_in[8];
    const float* w4 = (const float*)d_in[9];  const float* b4 = (const float*)d_in[10];
    const float* dw = (const float*)d_in[11]; const float* db = (const float*)d_in[12];
    float* out = (float*)d_out;

    float *h0, *h1, *h2, *o4, *sp, *xp;
    __nv_bfloat16 *bhi, *blo;
    unsigned long long *wfp;
    cudaGetSymbolAddress((void**)&h0, g_h0);
    cudaGetSymbolAddress((void**)&h1, g_h1);
    cudaGetSymbolAddress((void**)&h2, g_h2);
    cudaGetSymbolAddress((void**)&o4, g_o4);
    cudaGetSymbolAddress((void**)&sp, g_samp);
    cudaGetSymbolAddress((void**)&xp, g_xp);
    cudaGetSymbolAddress((void**)&bhi, g_bhi);
    cudaGetSymbolAddress((void**)&blo, g_blo);
    cudaGetSymbolAddress((void**)&wfp, g_wf);

    {
        int n4 = 2 * C * HW / 4;
        zero_k<<<(n4 + 255) / 256, 256>>>((float4*)(out + (size_t)6 * C * HW), n4);
    }
    pad_k<<<(T * PPIX + 127) / 128, 128>>>(x, (float4*)xp);
    wprep_k<<<(WF_ELEMS + 255) / 256, 256>>>(w4, wfp);
    warp_concat_k<<<(NB * HW + 255) / 256, 256>>>(x, (const float4*)xp, fb, ff, h0);

    dim3 cb(32, 4);
    conv3x3_k<true><<<dim3(3, 72, 4), cb>>>(h0, w1, b1, h1, CIN1, C);
    conv3x3_k<true><<<dim3(3, 72, 4), cb>>>(h1, w2, b2, h2, C,    C);
    conv3x3_k<true><<<dim3(3, 72, 4), cb>>>(h2, w3, b3, h1, C,    C);

    padbf16_k<<<(NB * PPIX2 + 127) / 128, 128>>>(h1, bhi, blo);

    cudaFuncSetAttribute(conv4mma_k, cudaFuncAttributeMaxDynamicSharedMemorySize,
                         C4_SMEM);
    conv4mma_k<<<dim3(96, 3, NB), 128, C4_SMEM>>>(bhi, blo, wfp, b4, o4);

    sample_k<<<dim3(72, 16, NB), 128>>>((const float4*)xp, fb, ff, o4, (float4*)sp);

    cudaFuncSetAttribute(gemm_k, cudaFuncAttributeMaxDynamicSharedMemorySize,
                         GEMM_SMEM_BYTES);
    gemm_k<<<dim3(72, NB), 128, GEMM_SMEM_BYTES>>>((const float4*)sp, dw, db, out);
}